// round 10
// baseline (speedup 1.0000x reference)
#include <cuda_runtime.h>
#include <cuda_bf16.h>
#include <cstdint>

// Problem constants
#define SEQ     2048
#define BATCH   16
#define DMODEL  512
#define FFDIM   2048
#define MTOT    (SEQ*BATCH)          // 32768 token rows
#define CH      (BATCH*DMODEL)       // 8192 channels for the scan
#define ALPHA_F 0.9f
#define EPS_F   1e-5f

// Scan chunking
#define NCHUNK  16
#define CLEN    (SEQ/NCHUNK)         // 128

// ---------------- scratch (static device globals; no allocation) ------------
__device__ float g_y [(size_t)MTOT*DMODEL];   // LN output (tf32-rounded)
__device__ float g_z [(size_t)MTOT*DMODEL];   // projection output
__device__ float g_x1[(size_t)MTOT*DMODEL];   // x + attn
__device__ float g_h [(size_t)MTOT*FFDIM];    // relu hidden (tf32-rounded)
__device__ float g_E [NCHUNK*CH];             // chunk-local scan end values
__device__ float g_wl[(size_t)DMODEL*DMODEL]; // tf32-rounded weights
__device__ float g_w1[(size_t)FFDIM*DMODEL];
__device__ float g_w2[(size_t)DMODEL*FFDIM];

// ---------------- helpers ----------------------------------------------------
__device__ __forceinline__ float rnd_tf32(float f) {
    uint32_t u;
    asm("cvt.rna.tf32.f32 %0, %1;" : "=r"(u) : "f"(f));
    return __uint_as_float(u);
}

__device__ __forceinline__ void mma_tf32(float* c, const uint32_t* a, const uint32_t* b) {
    asm volatile(
        "mma.sync.aligned.m16n8k8.row.col.f32.tf32.tf32.f32 "
        "{%0,%1,%2,%3},{%4,%5,%6,%7},{%8,%9},{%0,%1,%2,%3};\n"
        : "+f"(c[0]), "+f"(c[1]), "+f"(c[2]), "+f"(c[3])
        : "r"(a[0]), "r"(a[1]), "r"(a[2]), "r"(a[3]),
          "r"(b[0]), "r"(b[1]));
}

__device__ __forceinline__ void cp_async16(uint32_t smem_addr, const void* gptr) {
    asm volatile("cp.async.cg.shared.global [%0], [%1], 16;\n"
                 :: "r"(smem_addr), "l"(gptr));
}

// ---------------- merged weight prep: round all 3 weights to tf32-RNA --------
#define N4_WL (DMODEL*DMODEL/4)   // 65536
#define N4_W1 (FFDIM*DMODEL/4)    // 262144
#define N4_W2 (DMODEL*FFDIM/4)    // 262144
#define N4_TOT (N4_WL + N4_W1 + N4_W2)

__global__ __launch_bounds__(256) void prep_all_kernel(
    const float* __restrict__ wl_s, float* __restrict__ wl_d,
    const float* __restrict__ w1_s, float* __restrict__ w1_d,
    const float* __restrict__ w2_s, float* __restrict__ w2_d)
{
    int i = blockIdx.x * 256 + threadIdx.x;
    if (i >= N4_TOT) return;
    const float4* s;
    float4* d;
    int j;
    if (i < N4_WL)              { s = (const float4*)wl_s; d = (float4*)wl_d; j = i; }
    else if (i < N4_WL + N4_W1) { s = (const float4*)w1_s; d = (float4*)w1_d; j = i - N4_WL; }
    else                        { s = (const float4*)w2_s; d = (float4*)w2_d; j = i - N4_WL - N4_W1; }
    float4 v = s[j];
    v.x = rnd_tf32(v.x); v.y = rnd_tf32(v.y);
    v.z = rnd_tf32(v.z); v.w = rnd_tf32(v.w);
    d[j] = v;
}

// ---------------- LayerNorm (LN1): one warp per row of 512; tf32-rounded -----
__global__ __launch_bounds__(256) void ln_kernel(
    const float* __restrict__ x, const float* __restrict__ gamma,
    const float* __restrict__ beta, float* __restrict__ y)
{
    int row  = blockIdx.x * 8 + (threadIdx.x >> 5);
    int lane = threadIdx.x & 31;
    const float4* xr = reinterpret_cast<const float4*>(x + (size_t)row * DMODEL);
    const float4* g4 = reinterpret_cast<const float4*>(gamma);
    const float4* b4 = reinterpret_cast<const float4*>(beta);
    float4* yr = reinterpret_cast<float4*>(y + (size_t)row * DMODEL);

    float4 v[4];
    float sum = 0.f, sq = 0.f;
#pragma unroll
    for (int i = 0; i < 4; i++) {
        v[i] = xr[lane + i * 32];
        sum += v[i].x + v[i].y + v[i].z + v[i].w;
        sq  += v[i].x*v[i].x + v[i].y*v[i].y + v[i].z*v[i].z + v[i].w*v[i].w;
    }
#pragma unroll
    for (int o = 16; o; o >>= 1) {
        sum += __shfl_xor_sync(0xffffffffu, sum, o);
        sq  += __shfl_xor_sync(0xffffffffu, sq,  o);
    }
    float m    = sum * (1.f / DMODEL);
    float var  = sq * (1.f / DMODEL) - m * m;
    float rstd = rsqrtf(var + EPS_F);
#pragma unroll
    for (int i = 0; i < 4; i++) {
        float4 gv = g4[lane + i * 32];
        float4 bv = b4[lane + i * 32];
        float4 o;
        o.x = rnd_tf32((v[i].x - m) * rstd * gv.x + bv.x);
        o.y = rnd_tf32((v[i].y - m) * rstd * gv.y + bv.y);
        o.z = rnd_tf32((v[i].z - m) * rstd * gv.z + bv.z);
        o.w = rnd_tf32((v[i].w - m) * rstd * gv.w + bv.w);
        yr[lane + i * 32] = o;
    }
}

// ---------------- tf32 tensor-core GEMM (R2-exact shape) ----------------------
// C = act(A*B^T + bias) [+ res].  A: [M,K] row-major fp32 (pre-rounded tf32).
// B: [N,K] row-major fp32 (pre-rounded tf32).
// BM=128, BN=128, BK=32, 3-stage cp.async pipeline, 256 threads = 8 warps
// (2 m-halves x 4 n-quarters), warp tile 64x32.
#define BM 128
#define BN 128
#define BK 32
#define NSTG 3
#define APITCH 36                      // 32 + 4 pad (words)
#define STAGE_WORDS (2 * BM * APITCH)  // A half + B half per stage (9216 words)
#define GEMM_SMEM_BYTES (NSTG * STAGE_WORDS * 4)  // 110592

template<bool RELU, bool RES, bool ROUND>
__global__ __launch_bounds__(256, 2) void gemm_tf32(
    const float* __restrict__ A, const float* __restrict__ B,
    const float* __restrict__ bias, const float* __restrict__ res,
    float* __restrict__ C, int M, int N, int K)
{
    extern __shared__ uint32_t sm[];

    const int tid  = threadIdx.x;
    const int warp = tid >> 5;
    const int lane = tid & 31;
    const int wm   = warp >> 2;    // 0..1  (m half, 64 rows)
    const int wn   = warp & 3;     // 0..3  (n quarter, 32 cols)
    const int g    = lane >> 2;    // 0..7
    const int tg   = lane & 3;     // 0..3

    const int m0 = blockIdx.y * BM;
    const int n0 = blockIdx.x * BN;

    const int lr = tid >> 3;        // load row base (0..31)
    const int lc = (tid & 7) * 4;   // load col within BK

    const int nk = K / BK;

    float acc[4][4][4];
#pragma unroll
    for (int mt = 0; mt < 4; mt++)
#pragma unroll
        for (int nt = 0; nt < 4; nt++)
#pragma unroll
            for (int i = 0; i < 4; i++) acc[mt][nt][i] = 0.f;

#define AS(s, r, c) sm[(s) * STAGE_WORDS + (r) * APITCH + (c)]
#define BS(s, r, c) sm[(s) * STAGE_WORDS + BM * APITCH + (r) * APITCH + (c)]

    const float* Ag = A + (size_t)(m0 + lr) * K + lc;
    const float* Bg = B + (size_t)(n0 + lr) * K + lc;

    // prologue: fill stages 0..NSTG-2
#pragma unroll
    for (int s = 0; s < NSTG - 1; s++) {
#pragma unroll
        for (int r = 0; r < 4; r++) {
            cp_async16((uint32_t)__cvta_generic_to_shared(&AS(s, lr + 32 * r, lc)),
                       Ag + (size_t)32 * r * K + s * BK);
            cp_async16((uint32_t)__cvta_generic_to_shared(&BS(s, lr + 32 * r, lc)),
                       Bg + (size_t)32 * r * K + s * BK);
        }
        asm volatile("cp.async.commit_group;\n");
    }

    for (int k = 0; k < nk; k++) {
        asm volatile("cp.async.wait_group %0;\n" :: "n"(NSTG - 2));
        __syncthreads();

        // issue next stage (slot was fully consumed at iteration k-1)
        int kn = k + NSTG - 1;
        if (kn < nk) {
            int sn = kn % NSTG;
#pragma unroll
            for (int r = 0; r < 4; r++) {
                cp_async16((uint32_t)__cvta_generic_to_shared(&AS(sn, lr + 32 * r, lc)),
                           Ag + (size_t)32 * r * K + kn * BK);
                cp_async16((uint32_t)__cvta_generic_to_shared(&BS(sn, lr + 32 * r, lc)),
                           Bg + (size_t)32 * r * K + kn * BK);
            }
        }
        asm volatile("cp.async.commit_group;\n");   // (possibly empty) keeps group count fixed

        const int s = k % NSTG;
#pragma unroll
        for (int kk = 0; kk < 4; kk++) {
            uint32_t af[4][4], bf[4][2];
#pragma unroll
            for (int mt = 0; mt < 4; mt++) {
                int mr = wm * 64 + mt * 16;
                af[mt][0] = AS(s, mr + g,     kk * 8 + tg);
                af[mt][1] = AS(s, mr + g + 8, kk * 8 + tg);
                af[mt][2] = AS(s, mr + g,     kk * 8 + tg + 4);
                af[mt][3] = AS(s, mr + g + 8, kk * 8 + tg + 4);
            }
#pragma unroll
            for (int nt = 0; nt < 4; nt++) {
                int nr = wn * 32 + nt * 8;
                bf[nt][0] = BS(s, nr + g, kk * 8 + tg);
                bf[nt][1] = BS(s, nr + g, kk * 8 + tg + 4);
            }
#pragma unroll
            for (int mt = 0; mt < 4; mt++)
#pragma unroll
                for (int nt = 0; nt < 4; nt++)
                    mma_tf32(acc[mt][nt], af[mt], bf[nt]);
        }
    }

    // epilogue: bias (+relu) (+tf32 round) (+residual)
#pragma unroll
    for (int mt = 0; mt < 4; mt++) {
        int r0 = m0 + wm * 64 + mt * 16 + g;
#pragma unroll
        for (int nt = 0; nt < 4; nt++) {
            int cc = n0 + wn * 32 + nt * 8 + tg * 2;
            float bv0 = bias[cc], bv1 = bias[cc + 1];
            float v0 = acc[mt][nt][0] + bv0;
            float v1 = acc[mt][nt][1] + bv1;
            float v2 = acc[mt][nt][2] + bv0;
            float v3 = acc[mt][nt][3] + bv1;
            if (RELU) {
                v0 = fmaxf(v0, 0.f); v1 = fmaxf(v1, 0.f);
                v2 = fmaxf(v2, 0.f); v3 = fmaxf(v3, 0.f);
            }
            if (ROUND) {
                v0 = rnd_tf32(v0); v1 = rnd_tf32(v1);
                v2 = rnd_tf32(v2); v3 = rnd_tf32(v3);
            }
            if (RES) {
                const float* r1 = res + (size_t)r0 * N + cc;
                const float* r2 = res + (size_t)(r0 + 8) * N + cc;
                v0 += r1[0]; v1 += r1[1];
                v2 += r2[0]; v3 += r2[1];
            }
            *reinterpret_cast<float2*>(&C[(size_t)r0 * N + cc])       = make_float2(v0, v1);
            *reinterpret_cast<float2*>(&C[(size_t)(r0 + 8) * N + cc]) = make_float2(v2, v3);
        }
    }
#undef AS
#undef BS
}

// ---------------- scan pass1: chunk-local end values --------------------------
__global__ __launch_bounds__(256) void scan_pass1(const float* __restrict__ z)
{
    int ch    = blockIdx.x * 256 + threadIdx.x;   // 0..CH-1
    int chunk = blockIdx.y;
    const float* zp = z + (size_t)chunk * CLEN * CH + ch;
    float P = 0.f;
#pragma unroll 4
    for (int t = 0; t < CLEN; t++)
        P = ALPHA_F * (P + zp[(size_t)t * CH]);
    g_E[chunk * CH + ch] = P;
}

// ---------------- fused scan pass3 + LN2 --------------------------------------
// One block = 512 threads = all channels d of one batch b, one seq-chunk.
// Thread d carries the scan recurrence for channel (b,d); x1 is computed in
// register, written out, and immediately LayerNorm'd with a block-wide
// deterministic reduction (warp shuffle + 16-partial tree) -> y written
// tf32-rounded. Eliminates the 64MB x1 re-read of a separate LN kernel.
__global__ __launch_bounds__(512) void scan3_ln2_kernel(
    const float* __restrict__ x, const float* __restrict__ z,
    const float* __restrict__ g2, const float* __restrict__ be2,
    float* __restrict__ x1, float* __restrict__ y)
{
    const int b     = blockIdx.x;        // 0..15
    const int chunk = blockIdx.y;        // 0..15
    const int d     = threadIdx.x;       // 0..511
    const int ch    = b * DMODEL + d;
    const int i0    = chunk * CLEN;
    const int warp  = d >> 5;
    const int lane  = d & 31;

    __shared__ float s_sum[16], s_sq[16], s_mv[2];

    // inter-chunk carry (identical fp sequence to R9 -> x1 bit-identical)
    float aL = powf(ALPHA_F, (float)CLEN);
    float P = 0.f;
    for (int c = 0; c < chunk; c++)
        P = g_E[c * CH + ch] + aL * P;

    const float gv = g2[d], bv = be2[d];
    const float* zp = z  + (size_t)i0 * CH + ch;
    const float* xp = x  + (size_t)i0 * CH + ch;
    float*       op = x1 + (size_t)i0 * CH + ch;
    float*       yp = y  + (size_t)i0 * CH + ch;

    float apow = powf(ALPHA_F, (float)(i0 + 1));           // a^{i0+1}
    float S    = ALPHA_F * (1.f - apow) / (1.f - ALPHA_F); // S_{i0+1}

    // prefetch t=0
    float zv = zp[0], xv = xp[0];

    for (int t = 0; t < CLEN; t++) {
        // issue next loads before the barriers so latency overlaps the LN
        float zn = 0.f, xn = 0.f;
        if (t + 1 < CLEN) {
            zn = zp[(size_t)(t + 1) * CH];
            xn = xp[(size_t)(t + 1) * CH];
        }

        P = ALPHA_F * (P + zv);
        float v = xv + P + (1.f - S) * zv;    // x1 value (same math as R9)
        op[(size_t)t * CH] = v;
        apow *= ALPHA_F;
        S += apow;

        // block-wide LN over the 512 values of this row
        float sum = v, sq = v * v;
#pragma unroll
        for (int o = 16; o; o >>= 1) {
            sum += __shfl_xor_sync(0xffffffffu, sum, o);
            sq  += __shfl_xor_sync(0xffffffffu, sq,  o);
        }
        if (lane == 0) { s_sum[warp] = sum; s_sq[warp] = sq; }
        __syncthreads();
        if (warp == 0) {
            float a = (lane < 16) ? s_sum[lane] : 0.f;
            float q = (lane < 16) ? s_sq[lane]  : 0.f;
#pragma unroll
            for (int o = 8; o; o >>= 1) {
                a += __shfl_xor_sync(0xffffffffu, a, o);
                q += __shfl_xor_sync(0xffffffffu, q, o);
            }
            if (lane == 0) { s_mv[0] = a; s_mv[1] = q; }
        }
        __syncthreads();
        float m    = s_mv[0] * (1.f / DMODEL);
        float var  = s_mv[1] * (1.f / DMODEL) - m * m;
        float rstd = rsqrtf(var + EPS_F);
        yp[(size_t)t * CH] = rnd_tf32((v - m) * rstd * gv + bv);

        zv = zn; xv = xn;
    }
}

// ---------------- launch -----------------------------------------------------
extern "C" void kernel_launch(void* const* d_in, const int* in_sizes, int n_in,
                              void* d_out, int out_size)
{
    const float* x     = (const float*)d_in[0];
    const float* w_lin = (const float*)d_in[1];
    const float* b_lin = (const float*)d_in[2];
    const float* w1    = (const float*)d_in[3];
    const float* b1    = (const float*)d_in[4];
    const float* w2    = (const float*)d_in[5];
    const float* b2    = (const float*)d_in[6];
    const float* g1    = (const float*)d_in[7];
    const float* be1   = (const float*)d_in[8];
    const float* g2    = (const float*)d_in[9];
    const float* be2   = (const float*)d_in[10];
    float* out = (float*)d_out;

    float *py, *pz, *px1, *ph, *pwl, *pw1, *pw2;
    cudaGetSymbolAddress((void**)&py,  g_y);
    cudaGetSymbolAddress((void**)&pz,  g_z);
    cudaGetSymbolAddress((void**)&px1, g_x1);
    cudaGetSymbolAddress((void**)&ph,  g_h);
    cudaGetSymbolAddress((void**)&pwl, g_wl);
    cudaGetSymbolAddress((void**)&pw1, g_w1);
    cudaGetSymbolAddress((void**)&pw2, g_w2);

    // allow >48KB dynamic smem (idempotent; safe under graph capture)
    cudaFuncSetAttribute(gemm_tf32<false, false, false>,
                         cudaFuncAttributeMaxDynamicSharedMemorySize, GEMM_SMEM_BYTES);
    cudaFuncSetAttribute(gemm_tf32<true, false, true>,
                         cudaFuncAttributeMaxDynamicSharedMemorySize, GEMM_SMEM_BYTES);
    cudaFuncSetAttribute(gemm_tf32<false, true, false>,
                         cudaFuncAttributeMaxDynamicSharedMemorySize, GEMM_SMEM_BYTES);

    // 0) round all weights to tf32-RNA in ONE launch
    prep_all_kernel<<<(N4_TOT + 255)/256, 256>>>(w_lin, pwl, w1, pw1, w2, pw2);

    // 1) y1 = LN(x; g1, be1)  (tf32-rounded output)
    ln_kernel<<<MTOT / 8, 256>>>(x, g1, be1, py);

    // 2) z = y1 * w_lin^T + b_lin   (M=32768, N=512, K=512)
    gemm_tf32<false, false, false><<<dim3(DMODEL / BN, MTOT / BM), 256, GEMM_SMEM_BYTES>>>(
        py, pwl, b_lin, nullptr, pz, MTOT, DMODEL, DMODEL);

    // 3) x1 = x + W*z  (chunk scan) fused with LN2 -> y2
    scan_pass1<<<dim3(CH / 256, NCHUNK), 256>>>(pz);
    scan3_ln2_kernel<<<dim3(BATCH, NCHUNK), 512>>>(x, pz, g2, be2, px1, py);

    // 5) h = relu(y2 * w1^T + b1), tf32-rounded   (N=2048, K=512)
    gemm_tf32<true, false, true><<<dim3(FFDIM / BN, MTOT / BM), 256, GEMM_SMEM_BYTES>>>(
        py, pw1, b1, nullptr, ph, MTOT, FFDIM, DMODEL);

    // 6) out = x1 + h * w2^T + b2   (N=512, K=2048)
    gemm_tf32<false, true, false><<<dim3(DMODEL / BN, MTOT / BM), 256, GEMM_SMEM_BYTES>>>(
        ph, pw2, b2, px1, out, MTOT, DMODEL, FFDIM);
}

// round 11
// speedup vs baseline: 1.0375x; 1.0375x over previous
#include <cuda_runtime.h>
#include <cuda_bf16.h>
#include <cstdint>

// Problem constants
#define SEQ     2048
#define BATCH   16
#define DMODEL  512
#define FFDIM   2048
#define MTOT    (SEQ*BATCH)          // 32768 token rows
#define CH      (BATCH*DMODEL)       // 8192 channels for the scan
#define CH4     (CH/4)               // 2048 float4 channels
#define ALPHA_F 0.9f
#define EPS_F   1e-5f

// Scan chunking (finer chunks: keeps grid full with float4-wide threads)
#define NCHUNK  32
#define CLEN    (SEQ/NCHUNK)         // 64

// ---------------- scratch (static device globals; no allocation) ------------
__device__ float g_y [(size_t)MTOT*DMODEL];   // LN output (tf32-rounded)
__device__ float g_z [(size_t)MTOT*DMODEL];   // projection output
__device__ float g_x1[(size_t)MTOT*DMODEL];   // x + attn
__device__ float g_h [(size_t)MTOT*FFDIM];    // relu hidden (tf32-rounded)
__device__ float g_E [NCHUNK*CH];             // chunk-local scan end values
__device__ float g_wl[(size_t)DMODEL*DMODEL]; // tf32-rounded weights
__device__ float g_w1[(size_t)FFDIM*DMODEL];
__device__ float g_w2[(size_t)DMODEL*FFDIM];

// ---------------- helpers ----------------------------------------------------
__device__ __forceinline__ float rnd_tf32(float f) {
    uint32_t u;
    asm("cvt.rna.tf32.f32 %0, %1;" : "=r"(u) : "f"(f));
    return __uint_as_float(u);
}

__device__ __forceinline__ void mma_tf32(float* c, const uint32_t* a, const uint32_t* b) {
    asm volatile(
        "mma.sync.aligned.m16n8k8.row.col.f32.tf32.tf32.f32 "
        "{%0,%1,%2,%3},{%4,%5,%6,%7},{%8,%9},{%0,%1,%2,%3};\n"
        : "+f"(c[0]), "+f"(c[1]), "+f"(c[2]), "+f"(c[3])
        : "r"(a[0]), "r"(a[1]), "r"(a[2]), "r"(a[3]),
          "r"(b[0]), "r"(b[1]));
}

__device__ __forceinline__ void cp_async16(uint32_t smem_addr, const void* gptr) {
    asm volatile("cp.async.cg.shared.global [%0], [%1], 16;\n"
                 :: "r"(smem_addr), "l"(gptr));
}

// ---------------- merged weight prep: round all 3 weights to tf32-RNA --------
#define N4_WL (DMODEL*DMODEL/4)   // 65536
#define N4_W1 (FFDIM*DMODEL/4)    // 262144
#define N4_W2 (DMODEL*FFDIM/4)    // 262144
#define N4_TOT (N4_WL + N4_W1 + N4_W2)

__global__ __launch_bounds__(256) void prep_all_kernel(
    const float* __restrict__ wl_s, float* __restrict__ wl_d,
    const float* __restrict__ w1_s, float* __restrict__ w1_d,
    const float* __restrict__ w2_s, float* __restrict__ w2_d)
{
    int i = blockIdx.x * 256 + threadIdx.x;
    if (i >= N4_TOT) return;
    const float4* s;
    float4* d;
    int j;
    if (i < N4_WL)              { s = (const float4*)wl_s; d = (float4*)wl_d; j = i; }
    else if (i < N4_WL + N4_W1) { s = (const float4*)w1_s; d = (float4*)w1_d; j = i - N4_WL; }
    else                        { s = (const float4*)w2_s; d = (float4*)w2_d; j = i - N4_WL - N4_W1; }
    float4 v = s[j];
    v.x = rnd_tf32(v.x); v.y = rnd_tf32(v.y);
    v.z = rnd_tf32(v.z); v.w = rnd_tf32(v.w);
    d[j] = v;
}

// ---------------- LayerNorm: one warp per row of 512; tf32-rounded output ----
__global__ __launch_bounds__(256) void ln_kernel(
    const float* __restrict__ x, const float* __restrict__ gamma,
    const float* __restrict__ beta, float* __restrict__ y)
{
    int row  = blockIdx.x * 8 + (threadIdx.x >> 5);
    int lane = threadIdx.x & 31;
    const float4* xr = reinterpret_cast<const float4*>(x + (size_t)row * DMODEL);
    const float4* g4 = reinterpret_cast<const float4*>(gamma);
    const float4* b4 = reinterpret_cast<const float4*>(beta);
    float4* yr = reinterpret_cast<float4*>(y + (size_t)row * DMODEL);

    float4 v[4];
    float sum = 0.f, sq = 0.f;
#pragma unroll
    for (int i = 0; i < 4; i++) {
        v[i] = xr[lane + i * 32];
        sum += v[i].x + v[i].y + v[i].z + v[i].w;
        sq  += v[i].x*v[i].x + v[i].y*v[i].y + v[i].z*v[i].z + v[i].w*v[i].w;
    }
#pragma unroll
    for (int o = 16; o; o >>= 1) {
        sum += __shfl_xor_sync(0xffffffffu, sum, o);
        sq  += __shfl_xor_sync(0xffffffffu, sq,  o);
    }
    float m    = sum * (1.f / DMODEL);
    float var  = sq * (1.f / DMODEL) - m * m;
    float rstd = rsqrtf(var + EPS_F);
#pragma unroll
    for (int i = 0; i < 4; i++) {
        float4 gv = g4[lane + i * 32];
        float4 bv = b4[lane + i * 32];
        float4 o;
        o.x = rnd_tf32((v[i].x - m) * rstd * gv.x + bv.x);
        o.y = rnd_tf32((v[i].y - m) * rstd * gv.y + bv.y);
        o.z = rnd_tf32((v[i].z - m) * rstd * gv.z + bv.z);
        o.w = rnd_tf32((v[i].w - m) * rstd * gv.w + bv.w);
        yr[lane + i * 32] = o;
    }
}

// ---------------- tf32 tensor-core GEMM (R2-exact shape) ----------------------
// C = act(A*B^T + bias) [+ res].  A: [M,K] row-major fp32 (pre-rounded tf32).
// B: [N,K] row-major fp32 (pre-rounded tf32).
// BM=128, BN=128, BK=32, 3-stage cp.async pipeline, 256 threads = 8 warps
// (2 m-halves x 4 n-quarters), warp tile 64x32.
#define BM 128
#define BN 128
#define BK 32
#define NSTG 3
#define APITCH 36                      // 32 + 4 pad (words)
#define STAGE_WORDS (2 * BM * APITCH)  // A half + B half per stage (9216 words)
#define GEMM_SMEM_BYTES (NSTG * STAGE_WORDS * 4)  // 110592

template<bool RELU, bool RES, bool ROUND>
__global__ __launch_bounds__(256, 2) void gemm_tf32(
    const float* __restrict__ A, const float* __restrict__ B,
    const float* __restrict__ bias, const float* __restrict__ res,
    float* __restrict__ C, int M, int N, int K)
{
    extern __shared__ uint32_t sm[];

    const int tid  = threadIdx.x;
    const int warp = tid >> 5;
    const int lane = tid & 31;
    const int wm   = warp >> 2;    // 0..1  (m half, 64 rows)
    const int wn   = warp & 3;     // 0..3  (n quarter, 32 cols)
    const int g    = lane >> 2;    // 0..7
    const int tg   = lane & 3;     // 0..3

    const int m0 = blockIdx.y * BM;
    const int n0 = blockIdx.x * BN;

    const int lr = tid >> 3;        // load row base (0..31)
    const int lc = (tid & 7) * 4;   // load col within BK

    const int nk = K / BK;

    float acc[4][4][4];
#pragma unroll
    for (int mt = 0; mt < 4; mt++)
#pragma unroll
        for (int nt = 0; nt < 4; nt++)
#pragma unroll
            for (int i = 0; i < 4; i++) acc[mt][nt][i] = 0.f;

#define AS(s, r, c) sm[(s) * STAGE_WORDS + (r) * APITCH + (c)]
#define BS(s, r, c) sm[(s) * STAGE_WORDS + BM * APITCH + (r) * APITCH + (c)]

    const float* Ag = A + (size_t)(m0 + lr) * K + lc;
    const float* Bg = B + (size_t)(n0 + lr) * K + lc;

    // prologue: fill stages 0..NSTG-2
#pragma unroll
    for (int s = 0; s < NSTG - 1; s++) {
#pragma unroll
        for (int r = 0; r < 4; r++) {
            cp_async16((uint32_t)__cvta_generic_to_shared(&AS(s, lr + 32 * r, lc)),
                       Ag + (size_t)32 * r * K + s * BK);
            cp_async16((uint32_t)__cvta_generic_to_shared(&BS(s, lr + 32 * r, lc)),
                       Bg + (size_t)32 * r * K + s * BK);
        }
        asm volatile("cp.async.commit_group;\n");
    }

    for (int k = 0; k < nk; k++) {
        asm volatile("cp.async.wait_group %0;\n" :: "n"(NSTG - 2));
        __syncthreads();

        // issue next stage (slot was fully consumed at iteration k-1)
        int kn = k + NSTG - 1;
        if (kn < nk) {
            int sn = kn % NSTG;
#pragma unroll
            for (int r = 0; r < 4; r++) {
                cp_async16((uint32_t)__cvta_generic_to_shared(&AS(sn, lr + 32 * r, lc)),
                           Ag + (size_t)32 * r * K + kn * BK);
                cp_async16((uint32_t)__cvta_generic_to_shared(&BS(sn, lr + 32 * r, lc)),
                           Bg + (size_t)32 * r * K + kn * BK);
            }
        }
        asm volatile("cp.async.commit_group;\n");   // (possibly empty) keeps group count fixed

        const int s = k % NSTG;
#pragma unroll
        for (int kk = 0; kk < 4; kk++) {
            uint32_t af[4][4], bf[4][2];
#pragma unroll
            for (int mt = 0; mt < 4; mt++) {
                int mr = wm * 64 + mt * 16;
                af[mt][0] = AS(s, mr + g,     kk * 8 + tg);
                af[mt][1] = AS(s, mr + g + 8, kk * 8 + tg);
                af[mt][2] = AS(s, mr + g,     kk * 8 + tg + 4);
                af[mt][3] = AS(s, mr + g + 8, kk * 8 + tg + 4);
            }
#pragma unroll
            for (int nt = 0; nt < 4; nt++) {
                int nr = wn * 32 + nt * 8;
                bf[nt][0] = BS(s, nr + g, kk * 8 + tg);
                bf[nt][1] = BS(s, nr + g, kk * 8 + tg + 4);
            }
#pragma unroll
            for (int mt = 0; mt < 4; mt++)
#pragma unroll
                for (int nt = 0; nt < 4; nt++)
                    mma_tf32(acc[mt][nt], af[mt], bf[nt]);
        }
    }

    // epilogue: bias (+relu) (+tf32 round) (+residual)
#pragma unroll
    for (int mt = 0; mt < 4; mt++) {
        int r0 = m0 + wm * 64 + mt * 16 + g;
#pragma unroll
        for (int nt = 0; nt < 4; nt++) {
            int cc = n0 + wn * 32 + nt * 8 + tg * 2;
            float bv0 = bias[cc], bv1 = bias[cc + 1];
            float v0 = acc[mt][nt][0] + bv0;
            float v1 = acc[mt][nt][1] + bv1;
            float v2 = acc[mt][nt][2] + bv0;
            float v3 = acc[mt][nt][3] + bv1;
            if (RELU) {
                v0 = fmaxf(v0, 0.f); v1 = fmaxf(v1, 0.f);
                v2 = fmaxf(v2, 0.f); v3 = fmaxf(v3, 0.f);
            }
            if (ROUND) {
                v0 = rnd_tf32(v0); v1 = rnd_tf32(v1);
                v2 = rnd_tf32(v2); v3 = rnd_tf32(v3);
            }
            if (RES) {
                const float* r1 = res + (size_t)r0 * N + cc;
                const float* r2 = res + (size_t)(r0 + 8) * N + cc;
                v0 += r1[0]; v1 += r1[1];
                v2 += r2[0]; v3 += r2[1];
            }
            *reinterpret_cast<float2*>(&C[(size_t)r0 * N + cc])       = make_float2(v0, v1);
            *reinterpret_cast<float2*>(&C[(size_t)(r0 + 8) * N + cc]) = make_float2(v2, v3);
        }
    }
#undef AS
#undef BS
}

// ---------------- causal exp-decay mixing: float4-wide chunked scan -----------
// attn_i = P_i + (1 - S_{i+1}) z_i,  P_i = a(P_{i-1} + z_i),  S_{i+1}=sum a^k
// Each thread carries 4 adjacent channels (rows are channel-contiguous ->
// 16B loads/stores, 4x MLP per thread).
__global__ __launch_bounds__(256) void scan_pass1(const float* __restrict__ z)
{
    int c4    = blockIdx.x * 256 + threadIdx.x;   // 0..CH4-1
    int chunk = blockIdx.y;
    const float4* zp = reinterpret_cast<const float4*>(z)
                     + (size_t)chunk * CLEN * CH4 + c4;
    float4 P = make_float4(0.f, 0.f, 0.f, 0.f);
#pragma unroll 4
    for (int t = 0; t < CLEN; t++) {
        float4 zv = zp[(size_t)t * CH4];
        P.x = ALPHA_F * (P.x + zv.x);
        P.y = ALPHA_F * (P.y + zv.y);
        P.z = ALPHA_F * (P.z + zv.z);
        P.w = ALPHA_F * (P.w + zv.w);
    }
    reinterpret_cast<float4*>(g_E)[(size_t)chunk * CH4 + c4] = P;
}

// pass3 with inlined carry (carry = E[c'] + aL*carry, ascending c')
__global__ __launch_bounds__(256) void scan_pass3(
    const float* __restrict__ x, const float* __restrict__ z, float* __restrict__ x1)
{
    int c4    = blockIdx.x * 256 + threadIdx.x;   // 0..CH4-1
    int chunk = blockIdx.y;
    int i0    = chunk * CLEN;

    float aL = powf(ALPHA_F, (float)CLEN);
    float4 P = make_float4(0.f, 0.f, 0.f, 0.f);
    const float4* E4 = reinterpret_cast<const float4*>(g_E);
    for (int c = 0; c < chunk; c++) {
        float4 e = E4[(size_t)c * CH4 + c4];
        P.x = e.x + aL * P.x;
        P.y = e.y + aL * P.y;
        P.z = e.z + aL * P.z;
        P.w = e.w + aL * P.w;
    }

    const float4* zp = reinterpret_cast<const float4*>(z) + (size_t)i0 * CH4 + c4;
    const float4* xp = reinterpret_cast<const float4*>(x) + (size_t)i0 * CH4 + c4;
    float4*       op = reinterpret_cast<float4*>(x1)      + (size_t)i0 * CH4 + c4;

    float apow = powf(ALPHA_F, (float)(i0 + 1));           // a^{i0+1}
    float S    = ALPHA_F * (1.f - apow) / (1.f - ALPHA_F); // S_{i0+1}
#pragma unroll 4
    for (int t = 0; t < CLEN; t++) {
        float4 zv = zp[(size_t)t * CH4];
        float4 xv = xp[(size_t)t * CH4];
        float w = 1.f - S;
        P.x = ALPHA_F * (P.x + zv.x);
        P.y = ALPHA_F * (P.y + zv.y);
        P.z = ALPHA_F * (P.z + zv.z);
        P.w = ALPHA_F * (P.w + zv.w);
        float4 o;
        o.x = xv.x + P.x + w * zv.x;
        o.y = xv.y + P.y + w * zv.y;
        o.z = xv.z + P.z + w * zv.z;
        o.w = xv.w + P.w + w * zv.w;
        op[(size_t)t * CH4] = o;
        apow *= ALPHA_F;
        S += apow;
    }
}

// ---------------- launch -----------------------------------------------------
extern "C" void kernel_launch(void* const* d_in, const int* in_sizes, int n_in,
                              void* d_out, int out_size)
{
    const float* x     = (const float*)d_in[0];
    const float* w_lin = (const float*)d_in[1];
    const float* b_lin = (const float*)d_in[2];
    const float* w1    = (const float*)d_in[3];
    const float* b1    = (const float*)d_in[4];
    const float* w2    = (const float*)d_in[5];
    const float* b2    = (const float*)d_in[6];
    const float* g1    = (const float*)d_in[7];
    const float* be1   = (const float*)d_in[8];
    const float* g2    = (const float*)d_in[9];
    const float* be2   = (const float*)d_in[10];
    float* out = (float*)d_out;

    float *py, *pz, *px1, *ph, *pwl, *pw1, *pw2;
    cudaGetSymbolAddress((void**)&py,  g_y);
    cudaGetSymbolAddress((void**)&pz,  g_z);
    cudaGetSymbolAddress((void**)&px1, g_x1);
    cudaGetSymbolAddress((void**)&ph,  g_h);
    cudaGetSymbolAddress((void**)&pwl, g_wl);
    cudaGetSymbolAddress((void**)&pw1, g_w1);
    cudaGetSymbolAddress((void**)&pw2, g_w2);

    // allow >48KB dynamic smem (idempotent; safe under graph capture)
    cudaFuncSetAttribute(gemm_tf32<false, false, false>,
                         cudaFuncAttributeMaxDynamicSharedMemorySize, GEMM_SMEM_BYTES);
    cudaFuncSetAttribute(gemm_tf32<true, false, true>,
                         cudaFuncAttributeMaxDynamicSharedMemorySize, GEMM_SMEM_BYTES);
    cudaFuncSetAttribute(gemm_tf32<false, true, false>,
                         cudaFuncAttributeMaxDynamicSharedMemorySize, GEMM_SMEM_BYTES);

    // 0) round all weights to tf32-RNA in ONE launch
    prep_all_kernel<<<(N4_TOT + 255)/256, 256>>>(w_lin, pwl, w1, pw1, w2, pw2);

    // 1) y1 = LN(x; g1, be1)  (tf32-rounded output)
    ln_kernel<<<MTOT / 8, 256>>>(x, g1, be1, py);

    // 2) z = y1 * w_lin^T + b_lin   (M=32768, N=512, K=512)
    gemm_tf32<false, false, false><<<dim3(DMODEL / BN, MTOT / BM), 256, GEMM_SMEM_BYTES>>>(
        py, pwl, b_lin, nullptr, pz, MTOT, DMODEL, DMODEL);

    // 3) x1 = x + W*z  via float4-wide chunked scan
    scan_pass1<<<dim3(CH4 / 256, NCHUNK), 256>>>(pz);
    scan_pass3<<<dim3(CH4 / 256, NCHUNK), 256>>>(x, pz, px1);

    // 4) y2 = LN(x1; g2, be2)  (tf32-rounded output)
    ln_kernel<<<MTOT / 8, 256>>>(px1, g2, be2, py);

    // 5) h = relu(y2 * w1^T + b1), tf32-rounded   (N=2048, K=512)
    gemm_tf32<true, false, true><<<dim3(FFDIM / BN, MTOT / BM), 256, GEMM_SMEM_BYTES>>>(
        py, pw1, b1, nullptr, ph, MTOT, FFDIM, DMODEL);

    // 6) out = x1 + h * w2^T + b2   (N=512, K=2048)
    gemm_tf32<false, true, false><<<dim3(DMODEL / BN, MTOT / BM), 256, GEMM_SMEM_BYTES>>>(
        ph, pw2, b2, px1, out, MTOT, DMODEL, FFDIM);
}

// round 12
// speedup vs baseline: 1.7883x; 1.7237x over previous
#include <cuda_runtime.h>
#include <cuda_fp16.h>
#include <cstdint>

// Problem constants
#define SEQ     2048
#define BATCH   16
#define DMODEL  512
#define FFDIM   2048
#define MTOT    (SEQ*BATCH)          // 32768 token rows
#define CH      (BATCH*DMODEL)       // 8192 channels for the scan
#define CH4     (CH/4)               // 2048 float4 channels
#define ALPHA_F 0.9f
#define EPS_F   1e-5f

// Scan chunking
#define NCHUNK  32
#define CLEN    (SEQ/NCHUNK)         // 64

// ---------------- scratch (static device globals; no allocation) ------------
__device__ __align__(16) __half g_y [(size_t)MTOT*DMODEL];   // LN output (fp16)
__device__ float  g_z [(size_t)MTOT*DMODEL];                 // projection output
__device__ float  g_x1[(size_t)MTOT*DMODEL];                 // x + attn
__device__ __align__(16) __half g_h [(size_t)MTOT*FFDIM];    // relu hidden (fp16)
__device__ float  g_E [NCHUNK*CH];                           // chunk scan ends
__device__ __align__(16) __half g_wl[(size_t)DMODEL*DMODEL]; // fp16 weights
__device__ __align__(16) __half g_w1[(size_t)FFDIM*DMODEL];
__device__ __align__(16) __half g_w2[(size_t)DMODEL*FFDIM];

// ---------------- helpers ----------------------------------------------------
__device__ __forceinline__ void mma_f16(float* c, const uint32_t* a, const uint32_t* b) {
    asm volatile(
        "mma.sync.aligned.m16n8k16.row.col.f32.f16.f16.f32 "
        "{%0,%1,%2,%3},{%4,%5,%6,%7},{%8,%9},{%0,%1,%2,%3};\n"
        : "+f"(c[0]), "+f"(c[1]), "+f"(c[2]), "+f"(c[3])
        : "r"(a[0]), "r"(a[1]), "r"(a[2]), "r"(a[3]),
          "r"(b[0]), "r"(b[1]));
}

__device__ __forceinline__ void cp_async16(uint32_t smem_addr, const void* gptr) {
    asm volatile("cp.async.cg.shared.global [%0], [%1], 16;\n"
                 :: "r"(smem_addr), "l"(gptr));
}

// ---------------- weight prep: fp32 -> fp16 (single launch) -------------------
#define N8_WL (DMODEL*DMODEL/8)   // 32768
#define N8_W1 (FFDIM*DMODEL/8)    // 131072
#define N8_W2 (DMODEL*FFDIM/8)    // 131072
#define N8_TOT (N8_WL + N8_W1 + N8_W2)

__global__ __launch_bounds__(256) void prep_all_kernel(
    const float* __restrict__ wl_s, __half* __restrict__ wl_d,
    const float* __restrict__ w1_s, __half* __restrict__ w1_d,
    const float* __restrict__ w2_s, __half* __restrict__ w2_d)
{
    int i = blockIdx.x * 256 + threadIdx.x;
    if (i >= N8_TOT) return;
    const float4* s;
    __half* d;
    int j;
    if (i < N8_WL)              { s = (const float4*)wl_s; d = wl_d; j = i; }
    else if (i < N8_WL + N8_W1) { s = (const float4*)w1_s; d = w1_d; j = i - N8_WL; }
    else                        { s = (const float4*)w2_s; d = w2_d; j = i - N8_WL - N8_W1; }
    float4 a = s[j * 2], b = s[j * 2 + 1];
    __half2 h0 = __floats2half2_rn(a.x, a.y);
    __half2 h1 = __floats2half2_rn(a.z, a.w);
    __half2 h2 = __floats2half2_rn(b.x, b.y);
    __half2 h3 = __floats2half2_rn(b.z, b.w);
    uint4 o;
    o.x = *reinterpret_cast<uint32_t*>(&h0);
    o.y = *reinterpret_cast<uint32_t*>(&h1);
    o.z = *reinterpret_cast<uint32_t*>(&h2);
    o.w = *reinterpret_cast<uint32_t*>(&h3);
    reinterpret_cast<uint4*>(d)[j] = o;
}

// ---------------- LayerNorm: one warp per row of 512; fp16 output ------------
__global__ __launch_bounds__(256) void ln_kernel(
    const float* __restrict__ x, const float* __restrict__ gamma,
    const float* __restrict__ beta, __half* __restrict__ y)
{
    int row  = blockIdx.x * 8 + (threadIdx.x >> 5);
    int lane = threadIdx.x & 31;
    const float4* xr = reinterpret_cast<const float4*>(x + (size_t)row * DMODEL);
    const float4* g4 = reinterpret_cast<const float4*>(gamma);
    const float4* b4 = reinterpret_cast<const float4*>(beta);
    uint2* yr = reinterpret_cast<uint2*>(y + (size_t)row * DMODEL);

    float4 v[4];
    float sum = 0.f, sq = 0.f;
#pragma unroll
    for (int i = 0; i < 4; i++) {
        v[i] = xr[lane + i * 32];
        sum += v[i].x + v[i].y + v[i].z + v[i].w;
        sq  += v[i].x*v[i].x + v[i].y*v[i].y + v[i].z*v[i].z + v[i].w*v[i].w;
    }
#pragma unroll
    for (int o = 16; o; o >>= 1) {
        sum += __shfl_xor_sync(0xffffffffu, sum, o);
        sq  += __shfl_xor_sync(0xffffffffu, sq,  o);
    }
    float m    = sum * (1.f / DMODEL);
    float var  = sq * (1.f / DMODEL) - m * m;
    float rstd = rsqrtf(var + EPS_F);
#pragma unroll
    for (int i = 0; i < 4; i++) {
        float4 gv = g4[lane + i * 32];
        float4 bv = b4[lane + i * 32];
        __half2 h0 = __floats2half2_rn((v[i].x - m) * rstd * gv.x + bv.x,
                                       (v[i].y - m) * rstd * gv.y + bv.y);
        __half2 h1 = __floats2half2_rn((v[i].z - m) * rstd * gv.z + bv.z,
                                       (v[i].w - m) * rstd * gv.w + bv.w);
        uint2 o;
        o.x = *reinterpret_cast<uint32_t*>(&h0);
        o.y = *reinterpret_cast<uint32_t*>(&h1);
        yr[lane + i * 32] = o;
    }
}

// ---------------- fp16 tensor-core GEMM (R2 geometry, m16n8k16) ---------------
// C = act(A*B^T + bias) [+ res].  A: [M,K] row-major fp16. B: [N,K] fp16.
// BM=128, BN=128, BK=64 halves (128B rows), APITCH=36 words (same byte layout
// as the proven R2 tf32 kernel), 3-stage cp.async, 256 threads = 8 warps
// (2 m-halves x 4 n-quarters), warp tile 64x32, k16 MMA (4 per slab).
#define BM 128
#define BN 128
#define BKH 64                         // K elements (halves) per slab
#define NSTG 3
#define APITCH 36                      // 32 words data (64 halves) + 4 pad
#define STAGE_WORDS (2 * BM * APITCH)  // 9216 words = 36864 B
#define GEMM_SMEM_BYTES (NSTG * STAGE_WORDS * 4)  // 110592

template<bool RELU, bool RES, bool OUTH>
__global__ __launch_bounds__(256, 2) void gemm_f16(
    const __half* __restrict__ A, const __half* __restrict__ B,
    const float* __restrict__ bias, const float* __restrict__ res,
    void* __restrict__ Cv, int M, int N, int K)
{
    extern __shared__ uint32_t sm[];

    const int tid  = threadIdx.x;
    const int warp = tid >> 5;
    const int lane = tid & 31;
    const int wm   = warp >> 2;    // 0..1  (m half, 64 rows)
    const int wn   = warp & 3;     // 0..3  (n quarter, 32 cols)
    const int g    = lane >> 2;    // 0..7
    const int tg   = lane & 3;     // 0..3

    const int m0 = blockIdx.y * BM;
    const int n0 = blockIdx.x * BN;

    const int lr = tid >> 3;        // load row base (0..31)
    const int lc = (tid & 7) * 8;   // load col within BKH (halves; 16B chunks)

    const int nk = K / BKH;

    float acc[4][4][4];
#pragma unroll
    for (int mt = 0; mt < 4; mt++)
#pragma unroll
        for (int nt = 0; nt < 4; nt++)
#pragma unroll
            for (int i = 0; i < 4; i++) acc[mt][nt][i] = 0.f;

#define AS(s, r, c) sm[(s) * STAGE_WORDS + (r) * APITCH + (c)]
#define BS(s, r, c) sm[(s) * STAGE_WORDS + BM * APITCH + (r) * APITCH + (c)]

    const __half* Ag = A + (size_t)(m0 + lr) * K + lc;
    const __half* Bg = B + (size_t)(n0 + lr) * K + lc;

#define LOAD_SLAB(slab, stg) do {                                                   \
    _Pragma("unroll")                                                               \
    for (int r = 0; r < 4; r++) {                                                   \
        cp_async16((uint32_t)__cvta_generic_to_shared(&AS(stg, lr + 32 * r, (lc>>1))), \
                   Ag + (size_t)32 * r * K + (size_t)(slab) * BKH);                 \
        cp_async16((uint32_t)__cvta_generic_to_shared(&BS(stg, lr + 32 * r, (lc>>1))), \
                   Bg + (size_t)32 * r * K + (size_t)(slab) * BKH);                 \
    }                                                                               \
} while (0)

    // prologue: fill stages 0..NSTG-2
#pragma unroll
    for (int s = 0; s < NSTG - 1; s++) {
        LOAD_SLAB(s, s);
        asm volatile("cp.async.commit_group;\n");
    }

    for (int k = 0; k < nk; k++) {
        asm volatile("cp.async.wait_group %0;\n" :: "n"(NSTG - 2));
        __syncthreads();

        int kn = k + NSTG - 1;
        if (kn < nk) {
            int sn = kn % NSTG;
            LOAD_SLAB(kn, sn);
        }
        asm volatile("cp.async.commit_group;\n");   // possibly empty; keeps count fixed

        const int s = k % NSTG;
#pragma unroll
        for (int kk = 0; kk < 4; kk++) {            // 4 k16 blocks per 64-half slab
            uint32_t af[4][4], bf[4][2];
#pragma unroll
            for (int mt = 0; mt < 4; mt++) {
                int mr = wm * 64 + mt * 16;
                // words: 8*kk + tg -> halves 16kk + 2tg (+1); +4 words -> +8 halves
                af[mt][0] = AS(s, mr + g,     kk * 8 + tg);
                af[mt][1] = AS(s, mr + g + 8, kk * 8 + tg);
                af[mt][2] = AS(s, mr + g,     kk * 8 + tg + 4);
                af[mt][3] = AS(s, mr + g + 8, kk * 8 + tg + 4);
            }
#pragma unroll
            for (int nt = 0; nt < 4; nt++) {
                int nr = wn * 32 + nt * 8;
                bf[nt][0] = BS(s, nr + g, kk * 8 + tg);
                bf[nt][1] = BS(s, nr + g, kk * 8 + tg + 4);
            }
#pragma unroll
            for (int mt = 0; mt < 4; mt++)
#pragma unroll
                for (int nt = 0; nt < 4; nt++)
                    mma_f16(acc[mt][nt], af[mt], bf[nt]);
        }
    }

    // epilogue: bias (+relu) (+residual); fp32 or fp16 output
#pragma unroll
    for (int mt = 0; mt < 4; mt++) {
        int r0 = m0 + wm * 64 + mt * 16 + g;
#pragma unroll
        for (int nt = 0; nt < 4; nt++) {
            int cc = n0 + wn * 32 + nt * 8 + tg * 2;
            float bv0 = bias[cc], bv1 = bias[cc + 1];
            float v0 = acc[mt][nt][0] + bv0;
            float v1 = acc[mt][nt][1] + bv1;
            float v2 = acc[mt][nt][2] + bv0;
            float v3 = acc[mt][nt][3] + bv1;
            if (RELU) {
                v0 = fmaxf(v0, 0.f); v1 = fmaxf(v1, 0.f);
                v2 = fmaxf(v2, 0.f); v3 = fmaxf(v3, 0.f);
            }
            if (RES) {
                const float* r1 = res + (size_t)r0 * N + cc;
                const float* r2 = res + (size_t)(r0 + 8) * N + cc;
                v0 += r1[0]; v1 += r1[1];
                v2 += r2[0]; v3 += r2[1];
            }
            if (OUTH) {
                __half* Ch = (__half*)Cv;
                __half2 h0 = __floats2half2_rn(v0, v1);
                __half2 h1 = __floats2half2_rn(v2, v3);
                *reinterpret_cast<__half2*>(&Ch[(size_t)r0 * N + cc])       = h0;
                *reinterpret_cast<__half2*>(&Ch[(size_t)(r0 + 8) * N + cc]) = h1;
            } else {
                float* C = (float*)Cv;
                *reinterpret_cast<float2*>(&C[(size_t)r0 * N + cc])       = make_float2(v0, v1);
                *reinterpret_cast<float2*>(&C[(size_t)(r0 + 8) * N + cc]) = make_float2(v2, v3);
            }
        }
    }
#undef AS
#undef BS
#undef LOAD_SLAB
}

// ---------------- causal exp-decay mixing: float4-wide chunked scan -----------
__global__ __launch_bounds__(256) void scan_pass1(const float* __restrict__ z)
{
    int c4    = blockIdx.x * 256 + threadIdx.x;   // 0..CH4-1
    int chunk = blockIdx.y;
    const float4* zp = reinterpret_cast<const float4*>(z)
                     + (size_t)chunk * CLEN * CH4 + c4;
    float4 P = make_float4(0.f, 0.f, 0.f, 0.f);
#pragma unroll 4
    for (int t = 0; t < CLEN; t++) {
        float4 zv = zp[(size_t)t * CH4];
        P.x = ALPHA_F * (P.x + zv.x);
        P.y = ALPHA_F * (P.y + zv.y);
        P.z = ALPHA_F * (P.z + zv.z);
        P.w = ALPHA_F * (P.w + zv.w);
    }
    reinterpret_cast<float4*>(g_E)[(size_t)chunk * CH4 + c4] = P;
}

__global__ __launch_bounds__(256) void scan_pass3(
    const float* __restrict__ x, const float* __restrict__ z, float* __restrict__ x1)
{
    int c4    = blockIdx.x * 256 + threadIdx.x;
    int chunk = blockIdx.y;
    int i0    = chunk * CLEN;

    float aL = powf(ALPHA_F, (float)CLEN);
    float4 P = make_float4(0.f, 0.f, 0.f, 0.f);
    const float4* E4 = reinterpret_cast<const float4*>(g_E);
    for (int c = 0; c < chunk; c++) {
        float4 e = E4[(size_t)c * CH4 + c4];
        P.x = e.x + aL * P.x;
        P.y = e.y + aL * P.y;
        P.z = e.z + aL * P.z;
        P.w = e.w + aL * P.w;
    }

    const float4* zp = reinterpret_cast<const float4*>(z) + (size_t)i0 * CH4 + c4;
    const float4* xp = reinterpret_cast<const float4*>(x) + (size_t)i0 * CH4 + c4;
    float4*       op = reinterpret_cast<float4*>(x1)      + (size_t)i0 * CH4 + c4;

    float apow = powf(ALPHA_F, (float)(i0 + 1));           // a^{i0+1}
    float S    = ALPHA_F * (1.f - apow) / (1.f - ALPHA_F); // S_{i0+1}
#pragma unroll 4
    for (int t = 0; t < CLEN; t++) {
        float4 zv = zp[(size_t)t * CH4];
        float4 xv = xp[(size_t)t * CH4];
        float w = 1.f - S;
        P.x = ALPHA_F * (P.x + zv.x);
        P.y = ALPHA_F * (P.y + zv.y);
        P.z = ALPHA_F * (P.z + zv.z);
        P.w = ALPHA_F * (P.w + zv.w);
        float4 o;
        o.x = xv.x + P.x + w * zv.x;
        o.y = xv.y + P.y + w * zv.y;
        o.z = xv.z + P.z + w * zv.z;
        o.w = xv.w + P.w + w * zv.w;
        op[(size_t)t * CH4] = o;
        apow *= ALPHA_F;
        S += apow;
    }
}

// ---------------- launch -----------------------------------------------------
extern "C" void kernel_launch(void* const* d_in, const int* in_sizes, int n_in,
                              void* d_out, int out_size)
{
    const float* x     = (const float*)d_in[0];
    const float* w_lin = (const float*)d_in[1];
    const float* b_lin = (const float*)d_in[2];
    const float* w1    = (const float*)d_in[3];
    const float* b1    = (const float*)d_in[4];
    const float* w2    = (const float*)d_in[5];
    const float* b2    = (const float*)d_in[6];
    const float* g1    = (const float*)d_in[7];
    const float* be1   = (const float*)d_in[8];
    const float* g2    = (const float*)d_in[9];
    const float* be2   = (const float*)d_in[10];
    float* out = (float*)d_out;

    __half *py, *ph, *pwl, *pw1, *pw2;
    float *pz, *px1;
    cudaGetSymbolAddress((void**)&py,  g_y);
    cudaGetSymbolAddress((void**)&pz,  g_z);
    cudaGetSymbolAddress((void**)&px1, g_x1);
    cudaGetSymbolAddress((void**)&ph,  g_h);
    cudaGetSymbolAddress((void**)&pwl, g_wl);
    cudaGetSymbolAddress((void**)&pw1, g_w1);
    cudaGetSymbolAddress((void**)&pw2, g_w2);

    // allow >48KB dynamic smem (idempotent; safe under graph capture)
    cudaFuncSetAttribute(gemm_f16<false, false, false>,
                         cudaFuncAttributeMaxDynamicSharedMemorySize, GEMM_SMEM_BYTES);
    cudaFuncSetAttribute(gemm_f16<true, false, true>,
                         cudaFuncAttributeMaxDynamicSharedMemorySize, GEMM_SMEM_BYTES);
    cudaFuncSetAttribute(gemm_f16<false, true, false>,
                         cudaFuncAttributeMaxDynamicSharedMemorySize, GEMM_SMEM_BYTES);

    // 0) convert all weights to fp16 in ONE launch
    prep_all_kernel<<<(N8_TOT + 255)/256, 256>>>(w_lin, pwl, w1, pw1, w2, pw2);

    // 1) y1 = LN(x; g1, be1)  (fp16 output)
    ln_kernel<<<MTOT / 8, 256>>>(x, g1, be1, py);

    // 2) z = y1 * w_lin^T + b_lin   (M=32768, N=512, K=512), f32 out
    gemm_f16<false, false, false><<<dim3(DMODEL / BN, MTOT / BM), 256, GEMM_SMEM_BYTES>>>(
        py, pwl, b_lin, nullptr, pz, MTOT, DMODEL, DMODEL);

    // 3) x1 = x + W*z  via float4-wide chunked scan (f32)
    scan_pass1<<<dim3(CH4 / 256, NCHUNK), 256>>>(pz);
    scan_pass3<<<dim3(CH4 / 256, NCHUNK), 256>>>(x, pz, px1);

    // 4) y2 = LN(x1; g2, be2)  (fp16 output)
    ln_kernel<<<MTOT / 8, 256>>>(px1, g2, be2, py);

    // 5) h = relu(y2 * w1^T + b1)   (N=2048, K=512), fp16 out
    gemm_f16<true, false, true><<<dim3(FFDIM / BN, MTOT / BM), 256, GEMM_SMEM_BYTES>>>(
        py, pw1, b1, nullptr, ph, MTOT, FFDIM, DMODEL);

    // 6) out = x1 + h * w2^T + b2   (N=512, K=2048), f32 out
    gemm_f16<false, true, false><<<dim3(DMODEL / BN, MTOT / BM), 256, GEMM_SMEM_BYTES>>>(
        ph, pw2, b2, px1, out, MTOT, DMODEL, FFDIM);
}

// round 14
// speedup vs baseline: 1.9590x; 1.0954x over previous
#include <cuda_runtime.h>
#include <cuda_fp16.h>
#include <cstdint>

// Problem constants
#define SEQ     2048
#define BATCH   16
#define DMODEL  512
#define FFDIM   2048
#define MTOT    (SEQ*BATCH)          // 32768 token rows
#define CH      (BATCH*DMODEL)       // 8192 channels for the scan
#define CH4     (CH/4)               // 2048 4-channel groups
#define ALPHA_F 0.9f
#define EPS_F   1e-5f

// Scan chunking
#define NCHUNK  32
#define CLEN    (SEQ/NCHUNK)         // 64

// ---------------- scratch (static device globals; no allocation) ------------
__device__ __align__(16) __half g_y [(size_t)MTOT*DMODEL];   // LN output (fp16)
__device__ __align__(16) __half g_z [(size_t)MTOT*DMODEL];   // projection (fp16)
__device__ float  g_x1[(size_t)MTOT*DMODEL];                 // x + attn (f32)
__device__ __align__(16) __half g_h [(size_t)MTOT*FFDIM];    // relu hidden (fp16)
__device__ float  g_E [NCHUNK*CH];                           // chunk scan ends
__device__ __align__(16) __half g_wl[(size_t)DMODEL*DMODEL]; // fp16 weights
__device__ __align__(16) __half g_w1[(size_t)FFDIM*DMODEL];
__device__ __align__(16) __half g_w2[(size_t)DMODEL*FFDIM];

// ---------------- helpers ----------------------------------------------------
__device__ __forceinline__ void mma_f16(float* c, const uint32_t* a, const uint32_t* b) {
    asm volatile(
        "mma.sync.aligned.m16n8k16.row.col.f32.f16.f16.f32 "
        "{%0,%1,%2,%3},{%4,%5,%6,%7},{%8,%9},{%0,%1,%2,%3};\n"
        : "+f"(c[0]), "+f"(c[1]), "+f"(c[2]), "+f"(c[3])
        : "r"(a[0]), "r"(a[1]), "r"(a[2]), "r"(a[3]),
          "r"(b[0]), "r"(b[1]));
}

__device__ __forceinline__ void ldsm_x4(uint32_t* r, uint32_t addr) {
    asm volatile("ldmatrix.sync.aligned.m8n8.x4.shared.b16 {%0,%1,%2,%3}, [%4];"
                 : "=r"(r[0]), "=r"(r[1]), "=r"(r[2]), "=r"(r[3]) : "r"(addr));
}

__device__ __forceinline__ void ldsm_x2(uint32_t* r, uint32_t addr) {
    asm volatile("ldmatrix.sync.aligned.m8n8.x2.shared.b16 {%0,%1}, [%2];"
                 : "=r"(r[0]), "=r"(r[1]) : "r"(addr));
}

__device__ __forceinline__ void cp_async16(uint32_t smem_addr, const void* gptr) {
    asm volatile("cp.async.cg.shared.global [%0], [%1], 16;\n"
                 :: "r"(smem_addr), "l"(gptr));
}

// ---------------- weight prep: fp32 -> fp16 (single launch) -------------------
#define N8_WL (DMODEL*DMODEL/8)   // 32768
#define N8_W1 (FFDIM*DMODEL/8)    // 131072
#define N8_W2 (DMODEL*FFDIM/8)    // 131072
#define N8_TOT (N8_WL + N8_W1 + N8_W2)

__global__ __launch_bounds__(256) void prep_all_kernel(
    const float* __restrict__ wl_s, __half* __restrict__ wl_d,
    const float* __restrict__ w1_s, __half* __restrict__ w1_d,
    const float* __restrict__ w2_s, __half* __restrict__ w2_d)
{
    int i = blockIdx.x * 256 + threadIdx.x;
    if (i >= N8_TOT) return;
    const float4* s;
    __half* d;
    int j;
    if (i < N8_WL)              { s = (const float4*)wl_s; d = wl_d; j = i; }
    else if (i < N8_WL + N8_W1) { s = (const float4*)w1_s; d = w1_d; j = i - N8_WL; }
    else                        { s = (const float4*)w2_s; d = w2_d; j = i - N8_WL - N8_W1; }
    float4 a = s[j * 2], b = s[j * 2 + 1];
    __half2 h0 = __floats2half2_rn(a.x, a.y);
    __half2 h1 = __floats2half2_rn(a.z, a.w);
    __half2 h2 = __floats2half2_rn(b.x, b.y);
    __half2 h3 = __floats2half2_rn(b.z, b.w);
    uint4 o;
    o.x = *reinterpret_cast<uint32_t*>(&h0);
    o.y = *reinterpret_cast<uint32_t*>(&h1);
    o.z = *reinterpret_cast<uint32_t*>(&h2);
    o.w = *reinterpret_cast<uint32_t*>(&h3);
    reinterpret_cast<uint4*>(d)[j] = o;
}

// ---------------- LayerNorm: one warp per row of 512; fp16 output ------------
__global__ __launch_bounds__(256) void ln_kernel(
    const float* __restrict__ x, const float* __restrict__ gamma,
    const float* __restrict__ beta, __half* __restrict__ y)
{
    int row  = blockIdx.x * 8 + (threadIdx.x >> 5);
    int lane = threadIdx.x & 31;
    const float4* xr = reinterpret_cast<const float4*>(x + (size_t)row * DMODEL);
    const float4* g4 = reinterpret_cast<const float4*>(gamma);
    const float4* b4 = reinterpret_cast<const float4*>(beta);
    uint2* yr = reinterpret_cast<uint2*>(y + (size_t)row * DMODEL);

    float4 v[4];
    float sum = 0.f, sq = 0.f;
#pragma unroll
    for (int i = 0; i < 4; i++) {
        v[i] = xr[lane + i * 32];
        sum += v[i].x + v[i].y + v[i].z + v[i].w;
        sq  += v[i].x*v[i].x + v[i].y*v[i].y + v[i].z*v[i].z + v[i].w*v[i].w;
    }
#pragma unroll
    for (int o = 16; o; o >>= 1) {
        sum += __shfl_xor_sync(0xffffffffu, sum, o);
        sq  += __shfl_xor_sync(0xffffffffu, sq,  o);
    }
    float m    = sum * (1.f / DMODEL);
    float var  = sq * (1.f / DMODEL) - m * m;
    float rstd = rsqrtf(var + EPS_F);
#pragma unroll
    for (int i = 0; i < 4; i++) {
        float4 gv = g4[lane + i * 32];
        float4 bv = b4[lane + i * 32];
        __half2 h0 = __floats2half2_rn((v[i].x - m) * rstd * gv.x + bv.x,
                                       (v[i].y - m) * rstd * gv.y + bv.y);
        __half2 h1 = __floats2half2_rn((v[i].z - m) * rstd * gv.z + bv.z,
                                       (v[i].w - m) * rstd * gv.w + bv.w);
        uint2 o;
        o.x = *reinterpret_cast<uint32_t*>(&h0);
        o.y = *reinterpret_cast<uint32_t*>(&h1);
        yr[lane + i * 32] = o;
    }
}

// ---------------- fp16 tensor-core GEMM (ldmatrix fragments) ------------------
// C = act(A*B^T + bias) [+ res].  A: [M,K] row-major fp16. B: [N,K] fp16.
// BM=128, BN=128, BKH=64 halves (128B rows), APITCH=36 words, 3-stage
// cp.async, 256 threads = 8 warps (2m x 4n), warp tile 64x32, k16 MMA.
// Fragments via ldmatrix: 8 instrs per kk instead of 24 scalar LDS.
#define BM 128
#define BN 128
#define BKH 64
#define NSTG 3
#define APITCH 36                      // 32 data words (64 halves) + 4 pad
#define STAGE_WORDS (2 * BM * APITCH)  // 9216 words
#define GEMM_SMEM_BYTES (NSTG * STAGE_WORDS * 4)  // 110592

template<bool RELU, bool RES, bool OUTH>
__global__ __launch_bounds__(256, 2) void gemm_f16(
    const __half* __restrict__ A, const __half* __restrict__ B,
    const float* __restrict__ bias, const float* __restrict__ res,
    void* __restrict__ Cv, int M, int N, int K)
{
    extern __shared__ uint32_t sm[];
    const uint32_t sbase = (uint32_t)__cvta_generic_to_shared(sm);

    const int tid  = threadIdx.x;
    const int warp = tid >> 5;
    const int lane = tid & 31;
    const int wm   = warp >> 2;    // 0..1  (m half, 64 rows)
    const int wn   = warp & 3;     // 0..3  (n quarter, 32 cols)
    const int g    = lane >> 2;    // 0..7
    const int tg   = lane & 3;     // 0..3

    const int m0 = blockIdx.y * BM;
    const int n0 = blockIdx.x * BN;

    const int lr = tid >> 3;        // load row base (0..31)
    const int lc = (tid & 7) * 8;   // load col within BKH (halves)

    const int nk = K / BKH;

    // ldmatrix per-lane address invariants (word offsets within a stage)
    const uint32_t aOff = (uint32_t)((wm * 64 + (lane & 15)) * APITCH + (lane >> 4) * 4);
    const uint32_t bOff = (uint32_t)(BM * APITCH
                         + (wn * 32 + (lane & 7)) * APITCH + ((lane >> 3) & 1) * 4);

    float acc[4][4][4];
#pragma unroll
    for (int mt = 0; mt < 4; mt++)
#pragma unroll
        for (int nt = 0; nt < 4; nt++)
#pragma unroll
            for (int i = 0; i < 4; i++) acc[mt][nt][i] = 0.f;

#define ASW(s, r, c) sm[(s) * STAGE_WORDS + (r) * APITCH + (c)]
#define BSW(s, r, c) sm[(s) * STAGE_WORDS + BM * APITCH + (r) * APITCH + (c)]

    const __half* Ag = A + (size_t)(m0 + lr) * K + lc;
    const __half* Bg = B + (size_t)(n0 + lr) * K + lc;

#define LOAD_SLAB(slab, stg) do {                                                   \
    _Pragma("unroll")                                                               \
    for (int r = 0; r < 4; r++) {                                                   \
        cp_async16((uint32_t)__cvta_generic_to_shared(&ASW(stg, lr + 32 * r, (lc>>1))), \
                   Ag + (size_t)32 * r * K + (size_t)(slab) * BKH);                 \
        cp_async16((uint32_t)__cvta_generic_to_shared(&BSW(stg, lr + 32 * r, (lc>>1))), \
                   Bg + (size_t)32 * r * K + (size_t)(slab) * BKH);                 \
    }                                                                               \
} while (0)

    // prologue: fill stages 0..NSTG-2
#pragma unroll
    for (int s = 0; s < NSTG - 1; s++) {
        LOAD_SLAB(s, s);
        asm volatile("cp.async.commit_group;\n");
    }

    for (int k = 0; k < nk; k++) {
        asm volatile("cp.async.wait_group %0;\n" :: "n"(NSTG - 2));
        __syncthreads();

        int kn = k + NSTG - 1;
        if (kn < nk) {
            int sn = kn % NSTG;
            LOAD_SLAB(kn, sn);
        }
        asm volatile("cp.async.commit_group;\n");   // possibly empty; keeps count fixed

        const int s = k % NSTG;
        const uint32_t stg = sbase + (uint32_t)(s * STAGE_WORDS) * 4;
        const uint32_t aBase = stg + aOff * 4;
        const uint32_t bBase = stg + bOff * 4;

#pragma unroll
        for (int kk = 0; kk < 4; kk++) {            // 4 k16 blocks per 64-half slab
            uint32_t af[4][4], bf[4][2];
#pragma unroll
            for (int mt = 0; mt < 4; mt++)
                ldsm_x4(af[mt], aBase + (uint32_t)(mt * 16 * APITCH + kk * 8) * 4);
#pragma unroll
            for (int nt = 0; nt < 4; nt++)
                ldsm_x2(bf[nt], bBase + (uint32_t)(nt * 8 * APITCH + kk * 8) * 4);
#pragma unroll
            for (int mt = 0; mt < 4; mt++)
#pragma unroll
                for (int nt = 0; nt < 4; nt++)
                    mma_f16(acc[mt][nt], af[mt], bf[nt]);
        }
    }

    // epilogue: bias (+relu) (+residual); fp32 or fp16 output
#pragma unroll
    for (int mt = 0; mt < 4; mt++) {
        int r0 = m0 + wm * 64 + mt * 16 + g;
#pragma unroll
        for (int nt = 0; nt < 4; nt++) {
            int cc = n0 + wn * 32 + nt * 8 + tg * 2;
            float bv0 = bias[cc], bv1 = bias[cc + 1];
            float v0 = acc[mt][nt][0] + bv0;
            float v1 = acc[mt][nt][1] + bv1;
            float v2 = acc[mt][nt][2] + bv0;
            float v3 = acc[mt][nt][3] + bv1;
            if (RELU) {
                v0 = fmaxf(v0, 0.f); v1 = fmaxf(v1, 0.f);
                v2 = fmaxf(v2, 0.f); v3 = fmaxf(v3, 0.f);
            }
            if (RES) {
                const float* r1 = res + (size_t)r0 * N + cc;
                const float* r2 = res + (size_t)(r0 + 8) * N + cc;
                v0 += r1[0]; v1 += r1[1];
                v2 += r2[0]; v3 += r2[1];
            }
            if (OUTH) {
                __half* Ch = (__half*)Cv;
                __half2 h0 = __floats2half2_rn(v0, v1);
                __half2 h1 = __floats2half2_rn(v2, v3);
                *reinterpret_cast<__half2*>(&Ch[(size_t)r0 * N + cc])       = h0;
                *reinterpret_cast<__half2*>(&Ch[(size_t)(r0 + 8) * N + cc]) = h1;
            } else {
                float* C = (float*)Cv;
                *reinterpret_cast<float2*>(&C[(size_t)r0 * N + cc])       = make_float2(v0, v1);
                *reinterpret_cast<float2*>(&C[(size_t)(r0 + 8) * N + cc]) = make_float2(v2, v3);
            }
        }
    }
#undef ASW
#undef BSW
#undef LOAD_SLAB
}

// ---------------- causal exp-decay mixing: chunked scan over fp16 z -----------
// attn_i = P_i + (1 - S_{i+1}) z_i,  P_i = a(P_{i-1} + z_i)
// Each thread carries 4 adjacent channels; z is fp16 (8B loads), x/x1 f32.
__global__ __launch_bounds__(256) void scan_pass1(const __half* __restrict__ z)
{
    int c4    = blockIdx.x * 256 + threadIdx.x;   // 0..CH4-1
    int chunk = blockIdx.y;
    const uint2* zp = reinterpret_cast<const uint2*>(z)
                    + (size_t)chunk * CLEN * CH4 + c4;
    float4 P = make_float4(0.f, 0.f, 0.f, 0.f);
#pragma unroll 4
    for (int t = 0; t < CLEN; t++) {
        uint2 r = zp[(size_t)t * CH4];
        float2 f0 = __half22float2(*reinterpret_cast<__half2*>(&r.x));
        float2 f1 = __half22float2(*reinterpret_cast<__half2*>(&r.y));
        P.x = ALPHA_F * (P.x + f0.x);
        P.y = ALPHA_F * (P.y + f0.y);
        P.z = ALPHA_F * (P.z + f1.x);
        P.w = ALPHA_F * (P.w + f1.y);
    }
    reinterpret_cast<float4*>(g_E)[(size_t)chunk * CH4 + c4] = P;
}

__global__ __launch_bounds__(256) void scan_pass3(
    const float* __restrict__ x, const __half* __restrict__ z, float* __restrict__ x1)
{
    int c4    = blockIdx.x * 256 + threadIdx.x;
    int chunk = blockIdx.y;
    int i0    = chunk * CLEN;

    float aL = powf(ALPHA_F, (float)CLEN);
    float4 P = make_float4(0.f, 0.f, 0.f, 0.f);
    const float4* E4 = reinterpret_cast<const float4*>(g_E);
    for (int c = 0; c < chunk; c++) {
        float4 e = E4[(size_t)c * CH4 + c4];
        P.x = e.x + aL * P.x;
        P.y = e.y + aL * P.y;
        P.z = e.z + aL * P.z;
        P.w = e.w + aL * P.w;
    }

    const uint2*  zp = reinterpret_cast<const uint2*>(z)  + (size_t)i0 * CH4 + c4;
    const float4* xp = reinterpret_cast<const float4*>(x) + (size_t)i0 * CH4 + c4;
    float4*       op = reinterpret_cast<float4*>(x1)      + (size_t)i0 * CH4 + c4;

    float apow = powf(ALPHA_F, (float)(i0 + 1));           // a^{i0+1}
    float S    = ALPHA_F * (1.f - apow) / (1.f - ALPHA_F); // S_{i0+1}
#pragma unroll 4
    for (int t = 0; t < CLEN; t++) {
        uint2 r = zp[(size_t)t * CH4];
        float2 f0 = __half22float2(*reinterpret_cast<__half2*>(&r.x));
        float2 f1 = __half22float2(*reinterpret_cast<__half2*>(&r.y));
        float4 xv = xp[(size_t)t * CH4];
        float w = 1.f - S;
        P.x = ALPHA_F * (P.x + f0.x);
        P.y = ALPHA_F * (P.y + f0.y);
        P.z = ALPHA_F * (P.z + f1.x);
        P.w = ALPHA_F * (P.w + f1.y);
        float4 o;
        o.x = xv.x + P.x + w * f0.x;
        o.y = xv.y + P.y + w * f0.y;
        o.z = xv.z + P.z + w * f1.x;
        o.w = xv.w + P.w + w * f1.y;
        op[(size_t)t * CH4] = o;
        apow *= ALPHA_F;
        S += apow;
    }
}

// ---------------- launch -----------------------------------------------------
extern "C" void kernel_launch(void* const* d_in, const int* in_sizes, int n_in,
                              void* d_out, int out_size)
{
    const float* x     = (const float*)d_in[0];
    const float* w_lin = (const float*)d_in[1];
    const float* b_lin = (const float*)d_in[2];
    const float* w1    = (const float*)d_in[3];
    const float* b1    = (const float*)d_in[4];
    const float* w2    = (const float*)d_in[5];
    const float* b2    = (const float*)d_in[6];
    const float* g1    = (const float*)d_in[7];
    const float* be1   = (const float*)d_in[8];
    const float* g2    = (const float*)d_in[9];
    const float* be2   = (const float*)d_in[10];
    float* out = (float*)d_out;

    __half *py, *pz, *ph, *pwl, *pw1, *pw2;
    float *px1;
    cudaGetSymbolAddress((void**)&py,  g_y);
    cudaGetSymbolAddress((void**)&pz,  g_z);
    cudaGetSymbolAddress((void**)&px1, g_x1);
    cudaGetSymbolAddress((void**)&ph,  g_h);
    cudaGetSymbolAddress((void**)&pwl, g_wl);
    cudaGetSymbolAddress((void**)&pw1, g_w1);
    cudaGetSymbolAddress((void**)&pw2, g_w2);

    // allow >48KB dynamic smem (idempotent; safe under graph capture)
    cudaFuncSetAttribute(gemm_f16<false, false, true>,
                         cudaFuncAttributeMaxDynamicSharedMemorySize, GEMM_SMEM_BYTES);
    cudaFuncSetAttribute(gemm_f16<true, false, true>,
                         cudaFuncAttributeMaxDynamicSharedMemorySize, GEMM_SMEM_BYTES);
    cudaFuncSetAttribute(gemm_f16<false, true, false>,
                         cudaFuncAttributeMaxDynamicSharedMemorySize, GEMM_SMEM_BYTES);

    // 0) convert all weights to fp16 in ONE launch
    prep_all_kernel<<<(N8_TOT + 255)/256, 256>>>(w_lin, pwl, w1, pw1, w2, pw2);

    // 1) y1 = LN(x; g1, be1)  (fp16 output)
    ln_kernel<<<MTOT / 8, 256>>>(x, g1, be1, py);

    // 2) z = y1 * w_lin^T + b_lin   (M=32768, N=512, K=512), fp16 out
    gemm_f16<false, false, true><<<dim3(DMODEL / BN, MTOT / BM), 256, GEMM_SMEM_BYTES>>>(
        py, pwl, b_lin, nullptr, pz, MTOT, DMODEL, DMODEL);

    // 3) x1 = x + W*z  via chunked scan (z fp16, x/x1 f32)
    scan_pass1<<<dim3(CH4 / 256, NCHUNK), 256>>>(pz);
    scan_pass3<<<dim3(CH4 / 256, NCHUNK), 256>>>(x, pz, px1);

    // 4) y2 = LN(x1; g2, be2)  (fp16 output)
    ln_kernel<<<MTOT / 8, 256>>>(px1, g2, be2, py);

    // 5) h = relu(y2 * w1^T + b1)   (N=2048, K=512), fp16 out
    gemm_f16<true, false, true><<<dim3(FFDIM / BN, MTOT / BM), 256, GEMM_SMEM_BYTES>>>(
        py, pw1, b1, nullptr, ph, MTOT, FFDIM, DMODEL);

    // 6) out = x1 + h * w2^T + b2   (N=512, K=2048), f32 out
    gemm_f16<false, true, false><<<dim3(DMODEL / BN, MTOT / BM), 256, GEMM_SMEM_BYTES>>>(
        ph, pw2, b2, px1, out, MTOT, DMODEL, FFDIM);
}

// round 15
// speedup vs baseline: 2.0353x; 1.0390x over previous
#include <cuda_runtime.h>
#include <cuda_fp16.h>
#include <cstdint>

// Problem constants
#define SEQ     2048
#define BATCH   16
#define DMODEL  512
#define FFDIM   2048
#define MTOT    (SEQ*BATCH)          // 32768 token rows
#define CH      (BATCH*DMODEL)       // 8192 channels for the scan
#define CH4     (CH/4)               // 2048 4-channel groups
#define ALPHA_F 0.9f
#define EPS_F   1e-5f

// Scan chunking (finer: more blocks, shorter serial chains)
#define NCHUNK  64
#define CLEN    (SEQ/NCHUNK)         // 32

// ---------------- scratch (static device globals; no allocation) ------------
__device__ __align__(16) __half g_y [(size_t)MTOT*DMODEL];   // LN output (fp16)
__device__ __align__(16) __half g_z [(size_t)MTOT*DMODEL];   // projection (fp16)
__device__ __align__(16) __half g_x1[(size_t)MTOT*DMODEL];   // x + attn (fp16)
__device__ __align__(16) __half g_h [(size_t)MTOT*FFDIM];    // relu hidden (fp16)
__device__ float  g_E [NCHUNK*CH];                           // chunk scan ends
__device__ __align__(16) __half g_wl[(size_t)DMODEL*DMODEL]; // fp16 weights
__device__ __align__(16) __half g_w1[(size_t)FFDIM*DMODEL];
__device__ __align__(16) __half g_w2[(size_t)DMODEL*FFDIM];

// ---------------- helpers ----------------------------------------------------
__device__ __forceinline__ void mma_f16(float* c, const uint32_t* a, const uint32_t* b) {
    asm volatile(
        "mma.sync.aligned.m16n8k16.row.col.f32.f16.f16.f32 "
        "{%0,%1,%2,%3},{%4,%5,%6,%7},{%8,%9},{%0,%1,%2,%3};\n"
        : "+f"(c[0]), "+f"(c[1]), "+f"(c[2]), "+f"(c[3])
        : "r"(a[0]), "r"(a[1]), "r"(a[2]), "r"(a[3]),
          "r"(b[0]), "r"(b[1]));
}

__device__ __forceinline__ void ldsm_x4(uint32_t* r, uint32_t addr) {
    asm volatile("ldmatrix.sync.aligned.m8n8.x4.shared.b16 {%0,%1,%2,%3}, [%4];"
                 : "=r"(r[0]), "=r"(r[1]), "=r"(r[2]), "=r"(r[3]) : "r"(addr));
}

__device__ __forceinline__ void cp_async16(uint32_t smem_addr, const void* gptr) {
    asm volatile("cp.async.cg.shared.global [%0], [%1], 16;\n"
                 :: "r"(smem_addr), "l"(gptr));
}

// ---------------- weight prep: fp32 -> fp16 (single launch) -------------------
#define N8_WL (DMODEL*DMODEL/8)   // 32768
#define N8_W1 (FFDIM*DMODEL/8)    // 131072
#define N8_W2 (DMODEL*FFDIM/8)    // 131072
#define N8_TOT (N8_WL + N8_W1 + N8_W2)

__global__ __launch_bounds__(256) void prep_all_kernel(
    const float* __restrict__ wl_s, __half* __restrict__ wl_d,
    const float* __restrict__ w1_s, __half* __restrict__ w1_d,
    const float* __restrict__ w2_s, __half* __restrict__ w2_d)
{
    int i = blockIdx.x * 256 + threadIdx.x;
    if (i >= N8_TOT) return;
    const float4* s;
    __half* d;
    int j;
    if (i < N8_WL)              { s = (const float4*)wl_s; d = wl_d; j = i; }
    else if (i < N8_WL + N8_W1) { s = (const float4*)w1_s; d = w1_d; j = i - N8_WL; }
    else                        { s = (const float4*)w2_s; d = w2_d; j = i - N8_WL - N8_W1; }
    float4 a = s[j * 2], b = s[j * 2 + 1];
    __half2 h0 = __floats2half2_rn(a.x, a.y);
    __half2 h1 = __floats2half2_rn(a.z, a.w);
    __half2 h2 = __floats2half2_rn(b.x, b.y);
    __half2 h3 = __floats2half2_rn(b.z, b.w);
    uint4 o;
    o.x = *reinterpret_cast<uint32_t*>(&h0);
    o.y = *reinterpret_cast<uint32_t*>(&h1);
    o.z = *reinterpret_cast<uint32_t*>(&h2);
    o.w = *reinterpret_cast<uint32_t*>(&h3);
    reinterpret_cast<uint4*>(d)[j] = o;
}

// ---------------- LayerNorm (f32 input): one warp per row; fp16 output -------
__global__ __launch_bounds__(256) void ln_kernel(
    const float* __restrict__ x, const float* __restrict__ gamma,
    const float* __restrict__ beta, __half* __restrict__ y)
{
    int row  = blockIdx.x * 8 + (threadIdx.x >> 5);
    int lane = threadIdx.x & 31;
    const float4* xr = reinterpret_cast<const float4*>(x + (size_t)row * DMODEL);
    const float4* g4 = reinterpret_cast<const float4*>(gamma);
    const float4* b4 = reinterpret_cast<const float4*>(beta);
    uint2* yr = reinterpret_cast<uint2*>(y + (size_t)row * DMODEL);

    float4 v[4];
    float sum = 0.f, sq = 0.f;
#pragma unroll
    for (int i = 0; i < 4; i++) {
        v[i] = xr[lane + i * 32];
        sum += v[i].x + v[i].y + v[i].z + v[i].w;
        sq  += v[i].x*v[i].x + v[i].y*v[i].y + v[i].z*v[i].z + v[i].w*v[i].w;
    }
#pragma unroll
    for (int o = 16; o; o >>= 1) {
        sum += __shfl_xor_sync(0xffffffffu, sum, o);
        sq  += __shfl_xor_sync(0xffffffffu, sq,  o);
    }
    float m    = sum * (1.f / DMODEL);
    float var  = sq * (1.f / DMODEL) - m * m;
    float rstd = rsqrtf(var + EPS_F);
#pragma unroll
    for (int i = 0; i < 4; i++) {
        float4 gv = g4[lane + i * 32];
        float4 bv = b4[lane + i * 32];
        __half2 h0 = __floats2half2_rn((v[i].x - m) * rstd * gv.x + bv.x,
                                       (v[i].y - m) * rstd * gv.y + bv.y);
        __half2 h1 = __floats2half2_rn((v[i].z - m) * rstd * gv.z + bv.z,
                                       (v[i].w - m) * rstd * gv.w + bv.w);
        uint2 o;
        o.x = *reinterpret_cast<uint32_t*>(&h0);
        o.y = *reinterpret_cast<uint32_t*>(&h1);
        yr[lane + i * 32] = o;
    }
}

// ---------------- LayerNorm (fp16 input): one warp per row; fp16 output ------
__global__ __launch_bounds__(256) void ln_h_kernel(
    const __half* __restrict__ x, const float* __restrict__ gamma,
    const float* __restrict__ beta, __half* __restrict__ y)
{
    int row  = blockIdx.x * 8 + (threadIdx.x >> 5);
    int lane = threadIdx.x & 31;
    const uint4* xr = reinterpret_cast<const uint4*>(x + (size_t)row * DMODEL);
    const float4* g4 = reinterpret_cast<const float4*>(gamma);
    const float4* b4 = reinterpret_cast<const float4*>(beta);
    uint2* yr = reinterpret_cast<uint2*>(y + (size_t)row * DMODEL);

    // each lane: 2 x uint4 = 16 halves
    float v[16];
    float sum = 0.f, sq = 0.f;
#pragma unroll
    for (int i = 0; i < 2; i++) {
        uint4 r = xr[lane + i * 32];
        float2 f0 = __half22float2(*reinterpret_cast<__half2*>(&r.x));
        float2 f1 = __half22float2(*reinterpret_cast<__half2*>(&r.y));
        float2 f2 = __half22float2(*reinterpret_cast<__half2*>(&r.z));
        float2 f3 = __half22float2(*reinterpret_cast<__half2*>(&r.w));
        v[i*8+0]=f0.x; v[i*8+1]=f0.y; v[i*8+2]=f1.x; v[i*8+3]=f1.y;
        v[i*8+4]=f2.x; v[i*8+5]=f2.y; v[i*8+6]=f3.x; v[i*8+7]=f3.y;
#pragma unroll
        for (int j = 0; j < 8; j++) { sum += v[i*8+j]; sq += v[i*8+j]*v[i*8+j]; }
    }
#pragma unroll
    for (int o = 16; o; o >>= 1) {
        sum += __shfl_xor_sync(0xffffffffu, sum, o);
        sq  += __shfl_xor_sync(0xffffffffu, sq,  o);
    }
    float m    = sum * (1.f / DMODEL);
    float var  = sq * (1.f / DMODEL) - m * m;
    float rstd = rsqrtf(var + EPS_F);
#pragma unroll
    for (int i = 0; i < 2; i++) {
        // columns for this uint4: (lane + i*32)*8 .. +7  -> float4 idx *2
        int c4 = (lane + i * 32) * 2;
        float4 ga = g4[c4],     gb = g4[c4 + 1];
        float4 ba = b4[c4],     bb = b4[c4 + 1];
        __half2 h0 = __floats2half2_rn((v[i*8+0]-m)*rstd*ga.x+ba.x, (v[i*8+1]-m)*rstd*ga.y+ba.y);
        __half2 h1 = __floats2half2_rn((v[i*8+2]-m)*rstd*ga.z+ba.z, (v[i*8+3]-m)*rstd*ga.w+ba.w);
        __half2 h2 = __floats2half2_rn((v[i*8+4]-m)*rstd*gb.x+bb.x, (v[i*8+5]-m)*rstd*gb.y+bb.y);
        __half2 h3 = __floats2half2_rn((v[i*8+6]-m)*rstd*gb.z+bb.z, (v[i*8+7]-m)*rstd*gb.w+bb.w);
        uint2 o0, o1;
        o0.x = *reinterpret_cast<uint32_t*>(&h0);
        o0.y = *reinterpret_cast<uint32_t*>(&h1);
        o1.x = *reinterpret_cast<uint32_t*>(&h2);
        o1.y = *reinterpret_cast<uint32_t*>(&h3);
        yr[c4]     = o0;
        yr[c4 + 1] = o1;
    }
}

// ---------------- fp16 tensor-core GEMM (ldmatrix, paired-B x4) ---------------
// C = act(A*B^T + bias) [+ fp16 res].  A: [M,K] fp16. B: [N,K] fp16.
// BM=128, BN=128, BKH=64 halves (128B rows), APITCH=36 words, 3-stage
// cp.async, 256 threads = 8 warps (2m x 4n), warp tile 64x32, k16 MMA.
// Fragments: 4 A-x4 + 2 paired B-x4 per kk (6 LDSM vs 8).
#define BM 128
#define BN 128
#define BKH 64
#define NSTG 3
#define APITCH 36                      // 32 data words (64 halves) + 4 pad
#define STAGE_WORDS (2 * BM * APITCH)  // 9216 words
#define GEMM_SMEM_BYTES (NSTG * STAGE_WORDS * 4)  // 110592

template<bool RELU, bool RES, bool OUTH>
__global__ __launch_bounds__(256, 2) void gemm_f16(
    const __half* __restrict__ A, const __half* __restrict__ B,
    const float* __restrict__ bias, const __half* __restrict__ res,
    void* __restrict__ Cv, int M, int N, int K)
{
    extern __shared__ uint32_t sm[];
    const uint32_t sbase = (uint32_t)__cvta_generic_to_shared(sm);

    const int tid  = threadIdx.x;
    const int warp = tid >> 5;
    const int lane = tid & 31;
    const int wm   = warp >> 2;    // 0..1  (m half, 64 rows)
    const int wn   = warp & 3;     // 0..3  (n quarter, 32 cols)
    const int g    = lane >> 2;    // 0..7
    const int tg   = lane & 3;     // 0..3
    const int q    = lane >> 3;    // 0..3 (B x4 quad)

    const int m0 = blockIdx.y * BM;
    const int n0 = blockIdx.x * BN;

    const int lr = tid >> 3;        // load row base (0..31)
    const int lc = (tid & 7) * 8;   // load col within BKH (halves)

    const int nk = K / BKH;

    // ldmatrix per-lane address invariants (word offsets within a stage)
    const uint32_t aOff = (uint32_t)((wm * 64 + (lane & 15)) * APITCH + (lane >> 4) * 4);
    // paired-B x4: quad q -> (nt offset q>>1, k-half q&1)
    const uint32_t bOff = (uint32_t)(BM * APITCH
                         + (wn * 32 + (q >> 1) * 8 + (lane & 7)) * APITCH + (q & 1) * 4);

    float acc[4][4][4];
#pragma unroll
    for (int mt = 0; mt < 4; mt++)
#pragma unroll
        for (int nt = 0; nt < 4; nt++)
#pragma unroll
            for (int i = 0; i < 4; i++) acc[mt][nt][i] = 0.f;

#define ASW(s, r, c) sm[(s) * STAGE_WORDS + (r) * APITCH + (c)]
#define BSW(s, r, c) sm[(s) * STAGE_WORDS + BM * APITCH + (r) * APITCH + (c)]

    const __half* Ag = A + (size_t)(m0 + lr) * K + lc;
    const __half* Bg = B + (size_t)(n0 + lr) * K + lc;

#define LOAD_SLAB(slab, stg) do {                                                   \
    _Pragma("unroll")                                                               \
    for (int r = 0; r < 4; r++) {                                                   \
        cp_async16((uint32_t)__cvta_generic_to_shared(&ASW(stg, lr + 32 * r, (lc>>1))), \
                   Ag + (size_t)32 * r * K + (size_t)(slab) * BKH);                 \
        cp_async16((uint32_t)__cvta_generic_to_shared(&BSW(stg, lr + 32 * r, (lc>>1))), \
                   Bg + (size_t)32 * r * K + (size_t)(slab) * BKH);                 \
    }                                                                               \
} while (0)

    // prologue: fill stages 0..NSTG-2
#pragma unroll
    for (int s = 0; s < NSTG - 1; s++) {
        LOAD_SLAB(s, s);
        asm volatile("cp.async.commit_group;\n");
    }

    for (int k = 0; k < nk; k++) {
        asm volatile("cp.async.wait_group %0;\n" :: "n"(NSTG - 2));
        __syncthreads();

        int kn = k + NSTG - 1;
        if (kn < nk) {
            int sn = kn % NSTG;
            LOAD_SLAB(kn, sn);
        }
        asm volatile("cp.async.commit_group;\n");   // possibly empty; keeps count fixed

        const int s = k % NSTG;
        const uint32_t stg = sbase + (uint32_t)(s * STAGE_WORDS) * 4;
        const uint32_t aBase = stg + aOff * 4;
        const uint32_t bBase = stg + bOff * 4;

#pragma unroll
        for (int kk = 0; kk < 4; kk++) {            // 4 k16 blocks per 64-half slab
            uint32_t af[4][4], bf[4][2];
#pragma unroll
            for (int mt = 0; mt < 4; mt++)
                ldsm_x4(af[mt], aBase + (uint32_t)(mt * 16 * APITCH + kk * 8) * 4);
#pragma unroll
            for (int p = 0; p < 2; p++) {
                uint32_t bq[4];
                ldsm_x4(bq, bBase + (uint32_t)(p * 16 * APITCH + kk * 8) * 4);
                bf[2*p][0]   = bq[0]; bf[2*p][1]   = bq[1];
                bf[2*p+1][0] = bq[2]; bf[2*p+1][1] = bq[3];
            }
#pragma unroll
            for (int mt = 0; mt < 4; mt++)
#pragma unroll
                for (int nt = 0; nt < 4; nt++)
                    mma_f16(acc[mt][nt], af[mt], bf[nt]);
        }
    }

    // epilogue: bias (+relu) (+fp16 residual); fp32 or fp16 output
#pragma unroll
    for (int mt = 0; mt < 4; mt++) {
        int r0 = m0 + wm * 64 + mt * 16 + g;
#pragma unroll
        for (int nt = 0; nt < 4; nt++) {
            int cc = n0 + wn * 32 + nt * 8 + tg * 2;
            float bv0 = bias[cc], bv1 = bias[cc + 1];
            float v0 = acc[mt][nt][0] + bv0;
            float v1 = acc[mt][nt][1] + bv1;
            float v2 = acc[mt][nt][2] + bv0;
            float v3 = acc[mt][nt][3] + bv1;
            if (RELU) {
                v0 = fmaxf(v0, 0.f); v1 = fmaxf(v1, 0.f);
                v2 = fmaxf(v2, 0.f); v3 = fmaxf(v3, 0.f);
            }
            if (RES) {
                __half2 r1 = *reinterpret_cast<const __half2*>(&res[(size_t)r0 * N + cc]);
                __half2 r2 = *reinterpret_cast<const __half2*>(&res[(size_t)(r0 + 8) * N + cc]);
                float2 f1 = __half22float2(r1);
                float2 f2 = __half22float2(r2);
                v0 += f1.x; v1 += f1.y;
                v2 += f2.x; v3 += f2.y;
            }
            if (OUTH) {
                __half* Ch = (__half*)Cv;
                __half2 h0 = __floats2half2_rn(v0, v1);
                __half2 h1 = __floats2half2_rn(v2, v3);
                *reinterpret_cast<__half2*>(&Ch[(size_t)r0 * N + cc])       = h0;
                *reinterpret_cast<__half2*>(&Ch[(size_t)(r0 + 8) * N + cc]) = h1;
            } else {
                float* C = (float*)Cv;
                *reinterpret_cast<float2*>(&C[(size_t)r0 * N + cc])       = make_float2(v0, v1);
                *reinterpret_cast<float2*>(&C[(size_t)(r0 + 8) * N + cc]) = make_float2(v2, v3);
            }
        }
    }
#undef ASW
#undef BSW
#undef LOAD_SLAB
}

// ---------------- causal exp-decay mixing: chunked scan (z fp16, x1 fp16) -----
// attn_i = P_i + (1 - S_{i+1}) z_i,  P_i = a(P_{i-1} + z_i)
__global__ __launch_bounds__(256) void scan_pass1(const __half* __restrict__ z)
{
    int c4    = blockIdx.x * 256 + threadIdx.x;   // 0..CH4-1
    int chunk = blockIdx.y;
    const uint2* zp = reinterpret_cast<const uint2*>(z)
                    + (size_t)chunk * CLEN * CH4 + c4;
    float4 P = make_float4(0.f, 0.f, 0.f, 0.f);
#pragma unroll
    for (int t = 0; t < CLEN; t++) {
        uint2 r = zp[(size_t)t * CH4];
        float2 f0 = __half22float2(*reinterpret_cast<__half2*>(&r.x));
        float2 f1 = __half22float2(*reinterpret_cast<__half2*>(&r.y));
        P.x = ALPHA_F * (P.x + f0.x);
        P.y = ALPHA_F * (P.y + f0.y);
        P.z = ALPHA_F * (P.z + f1.x);
        P.w = ALPHA_F * (P.w + f1.y);
    }
    reinterpret_cast<float4*>(g_E)[(size_t)chunk * CH4 + c4] = P;
}

__global__ __launch_bounds__(256) void scan_pass3(
    const float* __restrict__ x, const __half* __restrict__ z, __half* __restrict__ x1)
{
    int c4    = blockIdx.x * 256 + threadIdx.x;
    int chunk = blockIdx.y;
    int i0    = chunk * CLEN;

    float aL = powf(ALPHA_F, (float)CLEN);
    float4 P = make_float4(0.f, 0.f, 0.f, 0.f);
    const float4* E4 = reinterpret_cast<const float4*>(g_E);
#pragma unroll 4
    for (int c = 0; c < chunk; c++) {
        float4 e = E4[(size_t)c * CH4 + c4];
        P.x = e.x + aL * P.x;
        P.y = e.y + aL * P.y;
        P.z = e.z + aL * P.z;
        P.w = e.w + aL * P.w;
    }

    const uint2*  zp = reinterpret_cast<const uint2*>(z)  + (size_t)i0 * CH4 + c4;
    const float4* xp = reinterpret_cast<const float4*>(x) + (size_t)i0 * CH4 + c4;
    uint2*        op = reinterpret_cast<uint2*>(x1)       + (size_t)i0 * CH4 + c4;

    float apow = powf(ALPHA_F, (float)(i0 + 1));           // a^{i0+1}
    float S    = ALPHA_F * (1.f - apow) / (1.f - ALPHA_F); // S_{i0+1}
#pragma unroll
    for (int t = 0; t < CLEN; t++) {
        uint2 r = zp[(size_t)t * CH4];
        float2 f0 = __half22float2(*reinterpret_cast<__half2*>(&r.x));
        float2 f1 = __half22float2(*reinterpret_cast<__half2*>(&r.y));
        float4 xv = xp[(size_t)t * CH4];
        float w = 1.f - S;
        P.x = ALPHA_F * (P.x + f0.x);
        P.y = ALPHA_F * (P.y + f0.y);
        P.z = ALPHA_F * (P.z + f1.x);
        P.w = ALPHA_F * (P.w + f1.y);
        __half2 h0 = __floats2half2_rn(xv.x + P.x + w * f0.x,
                                       xv.y + P.y + w * f0.y);
        __half2 h1 = __floats2half2_rn(xv.z + P.z + w * f1.x,
                                       xv.w + P.w + w * f1.y);
        uint2 o;
        o.x = *reinterpret_cast<uint32_t*>(&h0);
        o.y = *reinterpret_cast<uint32_t*>(&h1);
        op[(size_t)t * CH4] = o;
        apow *= ALPHA_F;
        S += apow;
    }
}

// ---------------- launch -----------------------------------------------------
extern "C" void kernel_launch(void* const* d_in, const int* in_sizes, int n_in,
                              void* d_out, int out_size)
{
    const float* x     = (const float*)d_in[0];
    const float* w_lin = (const float*)d_in[1];
    const float* b_lin = (const float*)d_in[2];
    const float* w1    = (const float*)d_in[3];
    const float* b1    = (const float*)d_in[4];
    const float* w2    = (const float*)d_in[5];
    const float* b2    = (const float*)d_in[6];
    const float* g1    = (const float*)d_in[7];
    const float* be1   = (const float*)d_in[8];
    const float* g2    = (const float*)d_in[9];
    const float* be2   = (const float*)d_in[10];
    float* out = (float*)d_out;

    __half *py, *pz, *px1, *ph, *pwl, *pw1, *pw2;
    cudaGetSymbolAddress((void**)&py,  g_y);
    cudaGetSymbolAddress((void**)&pz,  g_z);
    cudaGetSymbolAddress((void**)&px1, g_x1);
    cudaGetSymbolAddress((void**)&ph,  g_h);
    cudaGetSymbolAddress((void**)&pwl, g_wl);
    cudaGetSymbolAddress((void**)&pw1, g_w1);
    cudaGetSymbolAddress((void**)&pw2, g_w2);

    // allow >48KB dynamic smem (idempotent; safe under graph capture)
    cudaFuncSetAttribute(gemm_f16<false, false, true>,
                         cudaFuncAttributeMaxDynamicSharedMemorySize, GEMM_SMEM_BYTES);
    cudaFuncSetAttribute(gemm_f16<true, false, true>,
                         cudaFuncAttributeMaxDynamicSharedMemorySize, GEMM_SMEM_BYTES);
    cudaFuncSetAttribute(gemm_f16<false, true, false>,
                         cudaFuncAttributeMaxDynamicSharedMemorySize, GEMM_SMEM_BYTES);

    // 0) convert all weights to fp16 in ONE launch
    prep_all_kernel<<<(N8_TOT + 255)/256, 256>>>(w_lin, pwl, w1, pw1, w2, pw2);

    // 1) y1 = LN(x; g1, be1)  (fp16 output)
    ln_kernel<<<MTOT / 8, 256>>>(x, g1, be1, py);

    // 2) z = y1 * w_lin^T + b_lin   (M=32768, N=512, K=512), fp16 out
    gemm_f16<false, false, true><<<dim3(DMODEL / BN, MTOT / BM), 256, GEMM_SMEM_BYTES>>>(
        py, pwl, b_lin, nullptr, pz, MTOT, DMODEL, DMODEL);

    // 3) x1 = x + W*z  via chunked scan (z fp16 -> x1 fp16)
    scan_pass1<<<dim3(CH4 / 256, NCHUNK), 256>>>(pz);
    scan_pass3<<<dim3(CH4 / 256, NCHUNK), 256>>>(x, pz, px1);

    // 4) y2 = LN(x1; g2, be2)  (fp16 in, fp16 out)
    ln_h_kernel<<<MTOT / 8, 256>>>(px1, g2, be2, py);

    // 5) h = relu(y2 * w1^T + b1)   (N=2048, K=512), fp16 out
    gemm_f16<true, false, true><<<dim3(FFDIM / BN, MTOT / BM), 256, GEMM_SMEM_BYTES>>>(
        py, pw1, b1, nullptr, ph, MTOT, FFDIM, DMODEL);

    // 6) out = x1 + h * w2^T + b2   (N=512, K=2048), f32 out, fp16 residual
    gemm_f16<false, true, false><<<dim3(DMODEL / BN, MTOT / BM), 256, GEMM_SMEM_BYTES>>>(
        ph, pw2, b2, px1, out, MTOT, DMODEL, FFDIM);
}